// round 3
// baseline (speedup 1.0000x reference)
#include <cuda_runtime.h>
#include <math.h>

#define NUM_HEADS 16
#define HEAD_DIM  64
#define SEQ_L     2048
#define BATCH     2
#define EMB_D     1024
#define D_MODEL   1024
#define M_TOK     (BATCH * SEQ_L)   // 4096

// ---------------- scratch (device globals: no allocation allowed) ----------
__device__ __align__(16) float g_Q[(size_t)BATCH * NUM_HEADS * SEQ_L * HEAD_DIM];
__device__ __align__(16) float g_K[(size_t)BATCH * NUM_HEADS * SEQ_L * HEAD_DIM];
__device__ __align__(16) float g_V[(size_t)BATCH * NUM_HEADS * SEQ_L * HEAD_DIM];
__device__ __align__(16) float g_Ctx[(size_t)M_TOK * D_MODEL];

// ---------------- SGEMM: C[M,N] = A[M,K] @ W[K,N] + bias ----------------
// BM=BN=128, BK=16, 256 threads, 8x8 microtile per thread.
// EPI==0: scatter into Q/K/V [b,h,l,d] layout.  EPI==1: plain row-major store.
#define BM 128
#define BN 128
#define BK 16
#define ASTR 132   // padded stride (floats); 132*4B = 528B = 33 x 16B lines
#define BSTR 132

template <int EPI>
__global__ __launch_bounds__(256, 2) void gemm_kernel(
    const float* __restrict__ Ain, const float* __restrict__ W,
    const float* __restrict__ bias, float* __restrict__ Cout,
    int Ndim, int Kdim)
{
    __shared__ float As[BK * ASTR];   // transposed: As[k][row]
    __shared__ float Bs[BK * BSTR];   // Bs[k][col]

    const float* A = (EPI == 1) ? (const float*)g_Ctx : Ain;

    const int tid = threadIdx.x;
    const int tx  = tid & 15;
    const int ty  = tid >> 4;
    const int rowBase = blockIdx.y * BM;
    const int colBase = blockIdx.x * BN;

    // loader mapping
    const int la_row = tid >> 1;          // 0..127
    const int la_k   = (tid & 1) * 8;     // 0 or 8
    const int lb_k   = tid >> 4;          // 0..15
    const int lb_c   = (tid & 15) * 8;    // 0..120

    const float* Aptr = A + (size_t)(rowBase + la_row) * Kdim + la_k;
    const float* Wptr = W + (size_t)lb_k * Ndim + colBase + lb_c;

    float acc[8][8];
#pragma unroll
    for (int i = 0; i < 8; i++)
#pragma unroll
        for (int j = 0; j < 8; j++) acc[i][j] = 0.f;

    for (int kt = 0; kt < Kdim; kt += BK) {
        float4 a0 = *(const float4*)(Aptr + kt);
        float4 a1 = *(const float4*)(Aptr + kt + 4);
        float4 b0 = *(const float4*)(Wptr + (size_t)kt * Ndim);
        float4 b1 = *(const float4*)(Wptr + (size_t)kt * Ndim + 4);
        __syncthreads();   // previous tile fully consumed
        As[(la_k + 0) * ASTR + la_row] = a0.x;
        As[(la_k + 1) * ASTR + la_row] = a0.y;
        As[(la_k + 2) * ASTR + la_row] = a0.z;
        As[(la_k + 3) * ASTR + la_row] = a0.w;
        As[(la_k + 4) * ASTR + la_row] = a1.x;
        As[(la_k + 5) * ASTR + la_row] = a1.y;
        As[(la_k + 6) * ASTR + la_row] = a1.z;
        As[(la_k + 7) * ASTR + la_row] = a1.w;
        *(float4*)&Bs[lb_k * BSTR + lb_c]     = b0;
        *(float4*)&Bs[lb_k * BSTR + lb_c + 4] = b1;
        __syncthreads();

#pragma unroll
        for (int k = 0; k < BK; k++) {
            float4 av0 = *(const float4*)&As[k * ASTR + ty * 8];
            float4 av1 = *(const float4*)&As[k * ASTR + ty * 8 + 4];
            float4 bv0 = *(const float4*)&Bs[k * BSTR + tx * 4];       // cols tx*4 .. +3
            float4 bv1 = *(const float4*)&Bs[k * BSTR + tx * 4 + 64];  // cols tx*4+64 .. +67
            float av[8] = {av0.x, av0.y, av0.z, av0.w, av1.x, av1.y, av1.z, av1.w};
            float bv[8] = {bv0.x, bv0.y, bv0.z, bv0.w, bv1.x, bv1.y, bv1.z, bv1.w};
#pragma unroll
            for (int i = 0; i < 8; i++)
#pragma unroll
                for (int j = 0; j < 8; j++)
                    acc[i][j] = fmaf(av[i], bv[j], acc[i][j]);
        }
    }

    if (EPI == 0) {
        // column tile [colBase, colBase+128) lies inside one of Q/K/V (1024-wide parts)
        const int part = colBase >> 10;
        float* dst = (part == 0) ? g_Q : ((part == 1) ? g_K : g_V);
#pragma unroll
        for (int i = 0; i < 8; i++) {
            const int m  = rowBase + ty * 8 + i;
            const int bb = m >> 11;            // batch
            const int l  = m & (SEQ_L - 1);    // position
#pragma unroll
            for (int j = 0; j < 8; j++) {
                const int n = colBase + tx * 4 + ((j < 4) ? j : (j + 60));
                const float v = acc[i][j] + bias[n];
                const int within = n & 1023;
                const int h = within >> 6;
                const int d = within & 63;
                dst[(((size_t)(bb * NUM_HEADS + h)) * SEQ_L + l) * HEAD_DIM + d] = v;
            }
        }
    } else {
#pragma unroll
        for (int i = 0; i < 8; i++) {
            const int m = rowBase + ty * 8 + i;
#pragma unroll
            for (int j = 0; j < 8; j++) {
                const int n = colBase + tx * 4 + ((j < 4) ? j : (j + 60));
                Cout[(size_t)m * Ndim + n] = acc[i][j] + bias[n];
            }
        }
    }
}

// ---------------- Flash attention (fp32, online softmax) ----------------
// One block = one (b,h, 64-query tile). 256 threads, each owns a 4x4 patch.
#define BR 64
#define BC 64
#define QSTR 68   // 17 x 16B lines -> odd line stride, 2-way max on strided float4 LDS
#define VSTR 64
#define FLASH_SMEM ((HEAD_DIM * QSTR * 2 + BC * VSTR + BC * QSTR) * 4)   // 68,608 B

__global__ __launch_bounds__(256, 2) void flash_kernel()
{
    extern __shared__ float sh[];
    float* Qs = sh;                      // [d][r]  (transposed)
    float* Ks = Qs + HEAD_DIM * QSTR;    // [d][c]  (transposed)
    float* Vs = Ks + HEAD_DIM * QSTR;    // [c][d]
    float* Ps = Vs + BC * VSTR;          // [c][r]  (transposed P)

    const int tid = threadIdx.x;
    const int tx  = tid & 15;            // key / head-dim group
    const int ty  = tid >> 4;            // query group
    const int q0  = blockIdx.x * BR;
    const int bh  = blockIdx.y;          // b*16 + h

    const float* Qg = g_Q + ((size_t)bh * SEQ_L + q0) * HEAD_DIM;
    const float* Kg = g_K + (size_t)bh * SEQ_L * HEAD_DIM;
    const float* Vg = g_V + (size_t)bh * SEQ_L * HEAD_DIM;

    // load Q tile once, transposed to [d][r]
#pragma unroll
    for (int p = 0; p < 4; p++) {
        const int u  = tid + p * 256;
        const int r  = u >> 4;
        const int d4 = (u & 15) << 2;
        float4 g = *(const float4*)(Qg + r * HEAD_DIM + d4);
        Qs[(d4 + 0) * QSTR + r] = g.x;
        Qs[(d4 + 1) * QSTR + r] = g.y;
        Qs[(d4 + 2) * QSTR + r] = g.z;
        Qs[(d4 + 3) * QSTR + r] = g.w;
    }

    float o[4][4];
    float mrun[4], lrun[4];
#pragma unroll
    for (int i = 0; i < 4; i++) {
        mrun[i] = -1e30f;
        lrun[i] = 0.f;
#pragma unroll
        for (int j = 0; j < 4; j++) o[i][j] = 0.f;
    }

    for (int kt = 0; kt < SEQ_L; kt += BC) {
        // load K (transposed) and V (natural) tiles
#pragma unroll
        for (int p = 0; p < 4; p++) {
            const int u  = tid + p * 256;
            const int c  = u >> 4;
            const int d4 = (u & 15) << 2;
            float4 gk = *(const float4*)(Kg + (size_t)(kt + c) * HEAD_DIM + d4);
            Ks[(d4 + 0) * QSTR + c] = gk.x;
            Ks[(d4 + 1) * QSTR + c] = gk.y;
            Ks[(d4 + 2) * QSTR + c] = gk.z;
            Ks[(d4 + 3) * QSTR + c] = gk.w;
            float4 gv = *(const float4*)(Vg + (size_t)(kt + c) * HEAD_DIM + d4);
            *(float4*)&Vs[c * VSTR + d4] = gv;
        }
        __syncthreads();

        // S = Q @ K^T  (thread patch: rows ty*4..+3, cols tx*4..+3)
        float s[4][4];
#pragma unroll
        for (int i = 0; i < 4; i++)
#pragma unroll
            for (int j = 0; j < 4; j++) s[i][j] = 0.f;

#pragma unroll
        for (int d = 0; d < HEAD_DIM; d++) {
            float4 qa = *(const float4*)&Qs[d * QSTR + ty * 4];
            float4 ka = *(const float4*)&Ks[d * QSTR + tx * 4];
            float qv[4] = {qa.x, qa.y, qa.z, qa.w};
            float kv[4] = {ka.x, ka.y, ka.z, ka.w};
#pragma unroll
            for (int i = 0; i < 4; i++)
#pragma unroll
                for (int j = 0; j < 4; j++)
                    s[i][j] = fmaf(qv[i], kv[j], s[i][j]);
        }

        // scale + online softmax (row groups of 16 lanes share a warp half)
#pragma unroll
        for (int i = 0; i < 4; i++) {
#pragma unroll
            for (int j = 0; j < 4; j++) s[i][j] *= 0.125f;  // 1/sqrt(64)

            float rm = fmaxf(fmaxf(s[i][0], s[i][1]), fmaxf(s[i][2], s[i][3]));
            rm = fmaxf(rm, __shfl_xor_sync(0xffffffffu, rm, 1, 16));
            rm = fmaxf(rm, __shfl_xor_sync(0xffffffffu, rm, 2, 16));
            rm = fmaxf(rm, __shfl_xor_sync(0xffffffffu, rm, 4, 16));
            rm = fmaxf(rm, __shfl_xor_sync(0xffffffffu, rm, 8, 16));

            const float mn    = fmaxf(mrun[i], rm);
            const float alpha = __expf(mrun[i] - mn);
            mrun[i] = mn;

            float rs = 0.f;
#pragma unroll
            for (int j = 0; j < 4; j++) {
                const float pe = __expf(s[i][j] - mn);
                s[i][j] = pe;
                rs += pe;
            }
            rs += __shfl_xor_sync(0xffffffffu, rs, 1, 16);
            rs += __shfl_xor_sync(0xffffffffu, rs, 2, 16);
            rs += __shfl_xor_sync(0xffffffffu, rs, 4, 16);
            rs += __shfl_xor_sync(0xffffffffu, rs, 8, 16);

            lrun[i] = lrun[i] * alpha + rs;
#pragma unroll
            for (int j = 0; j < 4; j++) o[i][j] *= alpha;
        }

        // stage P transposed [c][r]
#pragma unroll
        for (int i = 0; i < 4; i++)
#pragma unroll
            for (int j = 0; j < 4; j++)
                Ps[(tx * 4 + j) * QSTR + (ty * 4 + i)] = s[i][j];
        __syncthreads();

        // O += P @ V  (thread patch: rows ty*4..+3, dims tx*4..+3)
#pragma unroll
        for (int c = 0; c < BC; c++) {
            float4 pa = *(const float4*)&Ps[c * QSTR + ty * 4];
            float4 va = *(const float4*)&Vs[c * VSTR + tx * 4];
            float pv[4] = {pa.x, pa.y, pa.z, pa.w};
            float vv[4] = {va.x, va.y, va.z, va.w};
#pragma unroll
            for (int i = 0; i < 4; i++)
#pragma unroll
                for (int j = 0; j < 4; j++)
                    o[i][j] = fmaf(pv[i], vv[j], o[i][j]);
        }
        __syncthreads();   // Ps/Vs/Ks free for next tile
    }

    // normalize + write context [b, l, h*64+d]
    const int b = bh >> 4;
    const int h = bh & 15;
#pragma unroll
    for (int i = 0; i < 4; i++) {
        const float inv = 1.f / lrun[i];
        const int row = q0 + ty * 4 + i;
        float4 ov = make_float4(o[i][0] * inv, o[i][1] * inv, o[i][2] * inv, o[i][3] * inv);
        *(float4*)&g_Ctx[((size_t)(b * SEQ_L + row)) * D_MODEL + h * HEAD_DIM + tx * 4] = ov;
    }
}

// ---------------- launch ----------------
extern "C" void kernel_launch(void* const* d_in, const int* in_sizes, int n_in,
                              void* d_out, int out_size)
{
    (void)in_sizes; (void)n_in; (void)out_size;
    const float* x    = (const float*)d_in[0];
    const float* Wqkv = (const float*)d_in[1];
    const float* bqkv = (const float*)d_in[2];
    const float* Wout = (const float*)d_in[3];
    const float* bout = (const float*)d_in[4];
    float* out = (float*)d_out;

    // >48KB dynamic smem opt-in (idempotent; not a stream op, capture-safe)
    cudaFuncSetAttribute(flash_kernel, cudaFuncAttributeMaxDynamicSharedMemorySize,
                         FLASH_SMEM);

    dim3 g1(3 * D_MODEL / BN, M_TOK / BM);   // 24 x 32
    gemm_kernel<0><<<g1, 256>>>(x, Wqkv, bqkv, nullptr, 3 * D_MODEL, EMB_D);

    dim3 g2(SEQ_L / BR, BATCH * NUM_HEADS);  // 32 x 32
    flash_kernel<<<g2, 256, FLASH_SMEM>>>();

    dim3 g3(EMB_D / BN, M_TOK / BM);         // 8 x 32
    gemm_kernel<1><<<g3, 256>>>(nullptr, Wout, bout, out, EMB_D, D_MODEL);
}

// round 9
// speedup vs baseline: 1.0198x; 1.0198x over previous
#include <cuda_runtime.h>
#include <cuda_fp16.h>
#include <stdint.h>
#include <math.h>

#define NUM_HEADS 16
#define HEAD_DIM  64
#define SEQ_L     2048
#define BATCH     2
#define EMB_D     1024
#define D_MODEL   1024
#define M_TOK     (BATCH * SEQ_L)   // 4096

// ---------------- scratch (device globals: no allocation allowed) ----------
__device__ __align__(16) float g_Q[(size_t)BATCH * NUM_HEADS * SEQ_L * HEAD_DIM];
__device__ __align__(16) float g_K[(size_t)BATCH * NUM_HEADS * SEQ_L * HEAD_DIM];
__device__ __align__(16) float g_V[(size_t)BATCH * NUM_HEADS * SEQ_L * HEAD_DIM];
__device__ __align__(16) float g_Ctx[(size_t)M_TOK * D_MODEL];

// ================= PROVEN R3 fp32 SGEMM (QKV projection) ====================
#define BM 128
#define BN 128
#define BKF 16
#define ASTR 132
#define BSTR 132

__global__ __launch_bounds__(256, 2) void gemm_qkv_kernel(
    const float* __restrict__ A, const float* __restrict__ W,
    const float* __restrict__ bias, int Ndim, int Kdim)
{
    __shared__ float As[BKF * ASTR];
    __shared__ float Bs[BKF * BSTR];

    const int tid = threadIdx.x;
    const int tx  = tid & 15;
    const int ty  = tid >> 4;
    const int rowBase = blockIdx.y * BM;
    const int colBase = blockIdx.x * BN;

    const int la_row = tid >> 1;
    const int la_k   = (tid & 1) * 8;
    const int lb_k   = tid >> 4;
    const int lb_c   = (tid & 15) * 8;

    const float* Aptr = A + (size_t)(rowBase + la_row) * Kdim + la_k;
    const float* Wptr = W + (size_t)lb_k * Ndim + colBase + lb_c;

    float acc[8][8];
#pragma unroll
    for (int i = 0; i < 8; i++)
#pragma unroll
        for (int j = 0; j < 8; j++) acc[i][j] = 0.f;

    for (int kt = 0; kt < Kdim; kt += BKF) {
        float4 a0 = *(const float4*)(Aptr + kt);
        float4 a1 = *(const float4*)(Aptr + kt + 4);
        float4 b0 = *(const float4*)(Wptr + (size_t)kt * Ndim);
        float4 b1 = *(const float4*)(Wptr + (size_t)kt * Ndim + 4);
        __syncthreads();
        As[(la_k + 0) * ASTR + la_row] = a0.x;
        As[(la_k + 1) * ASTR + la_row] = a0.y;
        As[(la_k + 2) * ASTR + la_row] = a0.z;
        As[(la_k + 3) * ASTR + la_row] = a0.w;
        As[(la_k + 4) * ASTR + la_row] = a1.x;
        As[(la_k + 5) * ASTR + la_row] = a1.y;
        As[(la_k + 6) * ASTR + la_row] = a1.z;
        As[(la_k + 7) * ASTR + la_row] = a1.w;
        *(float4*)&Bs[lb_k * BSTR + lb_c]     = b0;
        *(float4*)&Bs[lb_k * BSTR + lb_c + 4] = b1;
        __syncthreads();

#pragma unroll
        for (int k = 0; k < BKF; k++) {
            float4 av0 = *(const float4*)&As[k * ASTR + ty * 8];
            float4 av1 = *(const float4*)&As[k * ASTR + ty * 8 + 4];
            float4 bv0 = *(const float4*)&Bs[k * BSTR + tx * 4];
            float4 bv1 = *(const float4*)&Bs[k * BSTR + tx * 4 + 64];
            float av[8] = {av0.x, av0.y, av0.z, av0.w, av1.x, av1.y, av1.z, av1.w};
            float bv[8] = {bv0.x, bv0.y, bv0.z, bv0.w, bv1.x, bv1.y, bv1.z, bv1.w};
#pragma unroll
            for (int i = 0; i < 8; i++)
#pragma unroll
                for (int j = 0; j < 8; j++)
                    acc[i][j] = fmaf(av[i], bv[j], acc[i][j]);
        }
    }

    const int part = colBase >> 10;
    float* dst = (part == 0) ? g_Q : ((part == 1) ? g_K : g_V);
#pragma unroll
    for (int i = 0; i < 8; i++) {
        const int m  = rowBase + ty * 8 + i;
        const int bb = m >> 11;
        const int l  = m & (SEQ_L - 1);
#pragma unroll
        for (int j = 0; j < 8; j++) {
            const int n = colBase + tx * 4 + ((j < 4) ? j : (j + 60));
            const float v = acc[i][j] + bias[n];
            const int within = n & 1023;
            const int h = within >> 6;
            const int d = within & 63;
            dst[(((size_t)(bb * NUM_HEADS + h)) * SEQ_L + l) * HEAD_DIM + d] = v;
        }
    }
}

// ================= PROVEN R3 fp32 flash attention ===========================
#define BR 64
#define BC 64
#define QSTR 68
#define VSTR 64
#define FLASH_SMEM ((HEAD_DIM * QSTR * 2 + BC * VSTR + BC * QSTR) * 4)

__global__ __launch_bounds__(256, 2) void flash_kernel()
{
    extern __shared__ float sh[];
    float* Qs = sh;
    float* Ks = Qs + HEAD_DIM * QSTR;
    float* Vs = Ks + HEAD_DIM * QSTR;
    float* Ps = Vs + BC * VSTR;

    const int tid = threadIdx.x;
    const int tx  = tid & 15;
    const int ty  = tid >> 4;
    const int q0  = blockIdx.x * BR;
    const int bh  = blockIdx.y;

    const float* Qg = g_Q + ((size_t)bh * SEQ_L + q0) * HEAD_DIM;
    const float* Kg = g_K + (size_t)bh * SEQ_L * HEAD_DIM;
    const float* Vg = g_V + (size_t)bh * SEQ_L * HEAD_DIM;

#pragma unroll
    for (int p = 0; p < 4; p++) {
        const int u  = tid + p * 256;
        const int r  = u >> 4;
        const int d4 = (u & 15) << 2;
        float4 g = *(const float4*)(Qg + r * HEAD_DIM + d4);
        Qs[(d4 + 0) * QSTR + r] = g.x;
        Qs[(d4 + 1) * QSTR + r] = g.y;
        Qs[(d4 + 2) * QSTR + r] = g.z;
        Qs[(d4 + 3) * QSTR + r] = g.w;
    }

    float o[4][4];
    float mrun[4], lrun[4];
#pragma unroll
    for (int i = 0; i < 4; i++) {
        mrun[i] = -1e30f; lrun[i] = 0.f;
#pragma unroll
        for (int j = 0; j < 4; j++) o[i][j] = 0.f;
    }

    for (int kt = 0; kt < SEQ_L; kt += BC) {
#pragma unroll
        for (int p = 0; p < 4; p++) {
            const int u  = tid + p * 256;
            const int cc = u >> 4;
            const int d4 = (u & 15) << 2;
            float4 gk = *(const float4*)(Kg + (size_t)(kt + cc) * HEAD_DIM + d4);
            Ks[(d4 + 0) * QSTR + cc] = gk.x;
            Ks[(d4 + 1) * QSTR + cc] = gk.y;
            Ks[(d4 + 2) * QSTR + cc] = gk.z;
            Ks[(d4 + 3) * QSTR + cc] = gk.w;
            float4 gv = *(const float4*)(Vg + (size_t)(kt + cc) * HEAD_DIM + d4);
            *(float4*)&Vs[cc * VSTR + d4] = gv;
        }
        __syncthreads();

        float s[4][4];
#pragma unroll
        for (int i = 0; i < 4; i++)
#pragma unroll
            for (int j = 0; j < 4; j++) s[i][j] = 0.f;

#pragma unroll
        for (int d = 0; d < HEAD_DIM; d++) {
            float4 qa = *(const float4*)&Qs[d * QSTR + ty * 4];
            float4 ka = *(const float4*)&Ks[d * QSTR + tx * 4];
            float qv[4] = {qa.x, qa.y, qa.z, qa.w};
            float kv[4] = {ka.x, ka.y, ka.z, ka.w};
#pragma unroll
            for (int i = 0; i < 4; i++)
#pragma unroll
                for (int j = 0; j < 4; j++)
                    s[i][j] = fmaf(qv[i], kv[j], s[i][j]);
        }

#pragma unroll
        for (int i = 0; i < 4; i++) {
#pragma unroll
            for (int j = 0; j < 4; j++) s[i][j] *= 0.125f;

            float rm = fmaxf(fmaxf(s[i][0], s[i][1]), fmaxf(s[i][2], s[i][3]));
            rm = fmaxf(rm, __shfl_xor_sync(0xffffffffu, rm, 1, 16));
            rm = fmaxf(rm, __shfl_xor_sync(0xffffffffu, rm, 2, 16));
            rm = fmaxf(rm, __shfl_xor_sync(0xffffffffu, rm, 4, 16));
            rm = fmaxf(rm, __shfl_xor_sync(0xffffffffu, rm, 8, 16));

            const float mn    = fmaxf(mrun[i], rm);
            const float alpha = __expf(mrun[i] - mn);
            mrun[i] = mn;

            float rs = 0.f;
#pragma unroll
            for (int j = 0; j < 4; j++) {
                const float pe = __expf(s[i][j] - mn);
                s[i][j] = pe;
                rs += pe;
            }
            rs += __shfl_xor_sync(0xffffffffu, rs, 1, 16);
            rs += __shfl_xor_sync(0xffffffffu, rs, 2, 16);
            rs += __shfl_xor_sync(0xffffffffu, rs, 4, 16);
            rs += __shfl_xor_sync(0xffffffffu, rs, 8, 16);

            lrun[i] = lrun[i] * alpha + rs;
#pragma unroll
            for (int j = 0; j < 4; j++) o[i][j] *= alpha;
        }

#pragma unroll
        for (int i = 0; i < 4; i++)
#pragma unroll
            for (int j = 0; j < 4; j++)
                Ps[(tx * 4 + j) * QSTR + (ty * 4 + i)] = s[i][j];
        __syncthreads();

#pragma unroll
        for (int cc = 0; cc < BC; cc++) {
            float4 pa = *(const float4*)&Ps[cc * QSTR + ty * 4];
            float4 va = *(const float4*)&Vs[cc * VSTR + tx * 4];
            float pv[4] = {pa.x, pa.y, pa.z, pa.w};
            float vv[4] = {va.x, va.y, va.z, va.w};
#pragma unroll
            for (int i = 0; i < 4; i++)
#pragma unroll
                for (int j = 0; j < 4; j++)
                    o[i][j] = fmaf(pv[i], vv[j], o[i][j]);
        }
        __syncthreads();
    }

    const int b = bh >> 4;
    const int h = bh & 15;
#pragma unroll
    for (int i = 0; i < 4; i++) {
        const float inv = 1.f / lrun[i];
        const int row = q0 + ty * 4 + i;
        float4 ov = make_float4(o[i][0] * inv, o[i][1] * inv, o[i][2] * inv, o[i][3] * inv);
        *(float4*)&g_Ctx[((size_t)(b * SEQ_L + row)) * D_MODEL + h * HEAD_DIM + tx * 4] = ov;
    }
}

// ========== NEW (bisect target): HMMA out-projection, fp32 in/out ==========
// out[M,N] = g_Ctx[M,K] @ Wout[K,N] + bias.  fp16 hi/lo split done IN-KERNEL
// during smem staging (no prep kernels).  CTA 128x128, 8 warps 32x64, BK=32.
#define BKH  32
#define TSTR 40    // padded smem row stride in halves (80 B)

__device__ __forceinline__ void mma_f16(float* c, const uint32_t* a,
                                        uint32_t b0, uint32_t b1) {
    asm volatile(
        "mma.sync.aligned.m16n8k16.row.col.f32.f16.f16.f32 "
        "{%0,%1,%2,%3}, {%4,%5,%6,%7}, {%8,%9}, {%0,%1,%2,%3};"
        : "+f"(c[0]), "+f"(c[1]), "+f"(c[2]), "+f"(c[3])
        : "r"(a[0]), "r"(a[1]), "r"(a[2]), "r"(a[3]), "r"(b0), "r"(b1));
}

__global__ __launch_bounds__(256) void gemm_out_hmma(
    const float* __restrict__ W,      // [K=1024][N=1024] row-major
    const float* __restrict__ bias,
    float* __restrict__ C)            // [M_TOK][1024]
{
    __shared__ __align__(16) __half sm[4][128 * TSTR];  // Ahi, Alo, Bhi[n][k], Blo[n][k]

    const int tid  = threadIdx.x;
    const int wid  = tid >> 5, lane = tid & 31;
    const int wm   = wid & 3;
    const int wn   = wid >> 2;
    const int g    = lane >> 2;
    const int tig  = lane & 3;
    const int rowBase = blockIdx.y * 128;
    const int colBase = blockIdx.x * 128;

    // A loader: 128 rows x 32 k fp32; thread -> row tid/2, k half (tid&1)*16
    const int lrow = tid >> 1;
    const int lc   = (tid & 1) * 16;
    // B loader: W rows are n-contiguous; thread -> k row tid/8, n segment (tid&7)*16
    const int krow = tid >> 3;           // 0..31
    const int nseg = (tid & 7) * 16;     // 0..112

    float acc[2][8][4];
#pragma unroll
    for (int mi = 0; mi < 2; mi++)
#pragma unroll
        for (int nf = 0; nf < 8; nf++)
#pragma unroll
            for (int q = 0; q < 4; q++) acc[mi][nf][q] = 0.f;

    for (int ch = 0; ch < D_MODEL / BKH; ch++) {
        // global loads (fp32)
        float av[16], bv[16];
        const float* ap = g_Ctx + (size_t)(rowBase + lrow) * D_MODEL + ch * BKH + lc;
        const float* wp = W + (size_t)(ch * BKH + krow) * D_MODEL + colBase + nseg;
#pragma unroll
        for (int q = 0; q < 4; q++) {
            *(float4*)&av[q * 4] = *(const float4*)(ap + q * 4);
            *(float4*)&bv[q * 4] = *(const float4*)(wp + q * 4);
        }
        __syncthreads();   // previous chunk consumed

        // stage A hi/lo (row-major, k contiguous)
        __align__(16) __half ah16[16], al16[16];
#pragma unroll
        for (int j = 0; j < 16; j++) {
            __half h = __float2half_rn(av[j]);
            ah16[j] = h;
            al16[j] = __float2half_rn(av[j] - __half2float(h));
        }
        *(uint4*)&sm[0][lrow * TSTR + lc]     = *(uint4*)&ah16[0];
        *(uint4*)&sm[0][lrow * TSTR + lc + 8] = *(uint4*)&ah16[8];
        *(uint4*)&sm[1][lrow * TSTR + lc]     = *(uint4*)&al16[0];
        *(uint4*)&sm[1][lrow * TSTR + lc + 8] = *(uint4*)&al16[8];

        // stage B hi/lo TRANSPOSED: sm[2/3][n][k] = W[k][n]
#pragma unroll
        for (int j = 0; j < 16; j++) {
            __half h = __float2half_rn(bv[j]);
            sm[2][(nseg + j) * TSTR + krow] = h;
            sm[3][(nseg + j) * TSTR + krow] = __float2half_rn(bv[j] - __half2float(h));
        }
        __syncthreads();

#pragma unroll
        for (int ks = 0; ks < 2; ks++) {
            const int kb = ks * 16 + tig * 2;
            uint32_t ah[2][4], al[2][4];
#pragma unroll
            for (int mi = 0; mi < 2; mi++) {
                const int r = wm * 32 + mi * 16 + g;
                ah[mi][0] = *(const uint32_t*)&sm[0][r * TSTR + kb];
                ah[mi][1] = *(const uint32_t*)&sm[0][(r + 8) * TSTR + kb];
                ah[mi][2] = *(const uint32_t*)&sm[0][r * TSTR + kb + 8];
                ah[mi][3] = *(const uint32_t*)&sm[0][(r + 8) * TSTR + kb + 8];
                al[mi][0] = *(const uint32_t*)&sm[1][r * TSTR + kb];
                al[mi][1] = *(const uint32_t*)&sm[1][(r + 8) * TSTR + kb];
                al[mi][2] = *(const uint32_t*)&sm[1][r * TSTR + kb + 8];
                al[mi][3] = *(const uint32_t*)&sm[1][(r + 8) * TSTR + kb + 8];
            }
#pragma unroll
            for (int nf = 0; nf < 8; nf++) {
                const int n = wn * 64 + nf * 8 + g;
                const uint32_t bh0 = *(const uint32_t*)&sm[2][n * TSTR + kb];
                const uint32_t bh1 = *(const uint32_t*)&sm[2][n * TSTR + kb + 8];
                const uint32_t bl0 = *(const uint32_t*)&sm[3][n * TSTR + kb];
                const uint32_t bl1 = *(const uint32_t*)&sm[3][n * TSTR + kb + 8];
#pragma unroll
                for (int mi = 0; mi < 2; mi++) {
                    mma_f16(acc[mi][nf], ah[mi], bh0, bh1);   // hi*hi
                    mma_f16(acc[mi][nf], ah[mi], bl0, bl1);   // hi*lo
                    mma_f16(acc[mi][nf], al[mi], bh0, bh1);   // lo*hi
                }
            }
        }
    }

    // epilogue: c0,c1 -> (row, 2tig), c2,c3 -> (row+8, 2tig)
#pragma unroll
    for (int mi = 0; mi < 2; mi++) {
        const int rbase = rowBase + wm * 32 + mi * 16 + g;
#pragma unroll
        for (int nf = 0; nf < 8; nf++) {
            const int col = colBase + wn * 64 + nf * 8 + 2 * tig;
            const float bx = __ldg(bias + col), by = __ldg(bias + col + 1);
            float2 v0 = make_float2(acc[mi][nf][0] + bx, acc[mi][nf][1] + by);
            float2 v1 = make_float2(acc[mi][nf][2] + bx, acc[mi][nf][3] + by);
            *(float2*)&C[(size_t)rbase * D_MODEL + col] = v0;
            *(float2*)&C[(size_t)(rbase + 8) * D_MODEL + col] = v1;
        }
    }
}

// ---------------- launch ----------------
extern "C" void kernel_launch(void* const* d_in, const int* in_sizes, int n_in,
                              void* d_out, int out_size)
{
    (void)in_sizes; (void)n_in; (void)out_size;
    const float* x    = (const float*)d_in[0];
    const float* Wqkv = (const float*)d_in[1];
    const float* bqkv = (const float*)d_in[2];
    const float* Wout = (const float*)d_in[3];
    const float* bout = (const float*)d_in[4];
    float* out = (float*)d_out;

    cudaFuncSetAttribute(flash_kernel, cudaFuncAttributeMaxDynamicSharedMemorySize,
                         FLASH_SMEM);

    // QKV projection — proven fp32 SIMT kernel
    gemm_qkv_kernel<<<dim3(3 * D_MODEL / BN, M_TOK / BM), 256>>>(
        x, Wqkv, bqkv, 3 * D_MODEL, EMB_D);

    // attention — proven fp32 flash
    flash_kernel<<<dim3(SEQ_L / BR, BATCH * NUM_HEADS), 256, FLASH_SMEM>>>();

    // output projection — HMMA bisect target (fp32 in/out, in-kernel fp16 split)
    gemm_out_hmma<<<dim3(D_MODEL / 128, M_TOK / 128), 256>>>(Wout, bout, out);
}

// round 12
// speedup vs baseline: 1.2368x; 1.2128x over previous
#include <cuda_runtime.h>
#include <cuda_fp16.h>
#include <stdint.h>
#include <math.h>

#define NUM_HEADS 16
#define HEAD_DIM  64
#define SEQ_L     2048
#define BATCH     2
#define EMB_D     1024
#define D_MODEL   1024
#define KDIM      1024
#define M_TOK     (BATCH * SEQ_L)   // 4096

// ---------------- scratch (device globals: no allocation allowed) ----------
// RULE (learned R4-R11): device globals may ONLY be referenced inside device
// code. NEVER pass them as kernel arguments from host code.
__device__ __align__(16) float g_Q[(size_t)BATCH * NUM_HEADS * SEQ_L * HEAD_DIM];
__device__ __align__(16) float g_K[(size_t)BATCH * NUM_HEADS * SEQ_L * HEAD_DIM];
__device__ __align__(16) float g_V[(size_t)BATCH * NUM_HEADS * SEQ_L * HEAD_DIM];
__device__ __align__(16) float g_Ctx[(size_t)M_TOK * D_MODEL];

// ---------------- helpers ----------------
__device__ __forceinline__ void mma_f16(float* c, const uint32_t* a,
                                        uint32_t b0, uint32_t b1) {
    asm volatile(
        "mma.sync.aligned.m16n8k16.row.col.f32.f16.f16.f32 "
        "{%0,%1,%2,%3}, {%4,%5,%6,%7}, {%8,%9}, {%0,%1,%2,%3};"
        : "+f"(c[0]), "+f"(c[1]), "+f"(c[2]), "+f"(c[3])
        : "r"(a[0]), "r"(a[1]), "r"(a[2]), "r"(a[3]), "r"(b0), "r"(b1));
}

// ========== HMMA GEMM (R9-proven core; fixed plumbing; fixed B loader) ======
// C[M,N] = A[M,1024] @ W[1024,N] + bias.  fp16 hi/lo split in-kernel.
// CTA 128x128, 8 warps 32x64, BK=32, static smem single buffer.
// EPI 0: A = param (x), scatter into Q/K/V [b,h,l,d].
// EPI 1: A = g_Ctx (device-side reference), row-major store to Cout.
#define BKH  32
#define TSTR 40    // padded smem row stride in halves (80 B)

template <int EPI>
__global__ __launch_bounds__(256) void gemm_hmma(
    const float* __restrict__ Ain,
    const float* __restrict__ W,      // [1024][Ndim] row-major
    const float* __restrict__ bias,
    float* __restrict__ Cout,
    int Ndim)
{
    __shared__ __align__(16) __half sm[4][128 * TSTR];  // Ahi, Alo, Bhi[n][k], Blo[n][k]

    const float* A = (EPI == 1) ? (const float*)g_Ctx : Ain;  // device-side ref

    const int tid  = threadIdx.x;
    const int wid  = tid >> 5, lane = tid & 31;
    const int wm   = wid & 3;
    const int wn   = wid >> 2;
    const int g    = lane >> 2;
    const int tig  = lane & 3;
    const int rowBase = blockIdx.y * 128;
    const int colBase = blockIdx.x * 128;

    // A loader: thread -> row tid/2, k half (tid&1)*16 (contiguous float4 x4)
    const int lrow = tid >> 1;
    const int lc   = (tid & 1) * 16;
    // B loader: thread -> n-column tid/2, k half (tid&1)*16 (16 strided reads)
    const int bn   = tid >> 1;
    const int bkh  = (tid & 1) * 16;

    const float* ap = A + (size_t)(rowBase + lrow) * KDIM + lc;
    const float* wp = W + (size_t)bkh * Ndim + colBase + bn;

    float acc[2][8][4];
#pragma unroll
    for (int mi = 0; mi < 2; mi++)
#pragma unroll
        for (int nf = 0; nf < 8; nf++)
#pragma unroll
            for (int q = 0; q < 4; q++) acc[mi][nf][q] = 0.f;

    for (int ch = 0; ch < KDIM / BKH; ch++) {
        // global loads (fp32)
        float av[16], bv[16];
        const size_t ka = (size_t)ch * BKH;
#pragma unroll
        for (int q = 0; q < 4; q++)
            *(float4*)&av[q * 4] = *(const float4*)(ap + ka + q * 4);
#pragma unroll
        for (int q = 0; q < 16; q++)
            bv[q] = wp[(ka + q) * (size_t)Ndim];
        __syncthreads();   // previous chunk consumed

        // stage A hi/lo: sm[0/1][row][k], contiguous uint4 stores
        __align__(16) __half hh[16], ll[16];
#pragma unroll
        for (int j = 0; j < 16; j++) {
            __half h = __float2half_rn(av[j]);
            hh[j] = h;
            ll[j] = __float2half_rn(av[j] - __half2float(h));
        }
        *(uint4*)&sm[0][lrow * TSTR + lc]     = *(uint4*)&hh[0];
        *(uint4*)&sm[0][lrow * TSTR + lc + 8] = *(uint4*)&hh[8];
        *(uint4*)&sm[1][lrow * TSTR + lc]     = *(uint4*)&ll[0];
        *(uint4*)&sm[1][lrow * TSTR + lc + 8] = *(uint4*)&ll[8];

        // stage B hi/lo: sm[2/3][n][k], contiguous uint4 stores (conflict-light)
#pragma unroll
        for (int j = 0; j < 16; j++) {
            __half h = __float2half_rn(bv[j]);
            hh[j] = h;
            ll[j] = __float2half_rn(bv[j] - __half2float(h));
        }
        *(uint4*)&sm[2][bn * TSTR + bkh]     = *(uint4*)&hh[0];
        *(uint4*)&sm[2][bn * TSTR + bkh + 8] = *(uint4*)&hh[8];
        *(uint4*)&sm[3][bn * TSTR + bkh]     = *(uint4*)&ll[0];
        *(uint4*)&sm[3][bn * TSTR + bkh + 8] = *(uint4*)&ll[8];
        __syncthreads();

        // ---- compute (byte-identical to R9's passing fragment code) ----
#pragma unroll
        for (int ks = 0; ks < 2; ks++) {
            const int kb = ks * 16 + tig * 2;
            uint32_t ah[2][4], al[2][4];
#pragma unroll
            for (int mi = 0; mi < 2; mi++) {
                const int r = wm * 32 + mi * 16 + g;
                ah[mi][0] = *(const uint32_t*)&sm[0][r * TSTR + kb];
                ah[mi][1] = *(const uint32_t*)&sm[0][(r + 8) * TSTR + kb];
                ah[mi][2] = *(const uint32_t*)&sm[0][r * TSTR + kb + 8];
                ah[mi][3] = *(const uint32_t*)&sm[0][(r + 8) * TSTR + kb + 8];
                al[mi][0] = *(const uint32_t*)&sm[1][r * TSTR + kb];
                al[mi][1] = *(const uint32_t*)&sm[1][(r + 8) * TSTR + kb];
                al[mi][2] = *(const uint32_t*)&sm[1][r * TSTR + kb + 8];
                al[mi][3] = *(const uint32_t*)&sm[1][(r + 8) * TSTR + kb + 8];
            }
#pragma unroll
            for (int nf = 0; nf < 8; nf++) {
                const int n = wn * 64 + nf * 8 + g;
                const uint32_t bh0 = *(const uint32_t*)&sm[2][n * TSTR + kb];
                const uint32_t bh1 = *(const uint32_t*)&sm[2][n * TSTR + kb + 8];
                const uint32_t bl0 = *(const uint32_t*)&sm[3][n * TSTR + kb];
                const uint32_t bl1 = *(const uint32_t*)&sm[3][n * TSTR + kb + 8];
#pragma unroll
                for (int mi = 0; mi < 2; mi++) {
                    mma_f16(acc[mi][nf], ah[mi], bh0, bh1);   // hi*hi
                    mma_f16(acc[mi][nf], ah[mi], bl0, bl1);   // hi*lo
                    mma_f16(acc[mi][nf], al[mi], bh0, bh1);   // lo*hi
                }
            }
        }
    }

    // epilogue: c0,c1 -> (row rbase, col 2tig), c2,c3 -> (row+8, col 2tig)
#pragma unroll
    for (int mi = 0; mi < 2; mi++) {
        const int rbase = rowBase + wm * 32 + mi * 16 + g;
#pragma unroll
        for (int nf = 0; nf < 8; nf++) {
            const int col = colBase + wn * 64 + nf * 8 + 2 * tig;
            const float bx = __ldg(bias + col), by = __ldg(bias + col + 1);
            float2 v0 = make_float2(acc[mi][nf][0] + bx, acc[mi][nf][1] + by);
            float2 v1 = make_float2(acc[mi][nf][2] + bx, acc[mi][nf][3] + by);
            if (EPI == 0) {
                // scatter into Q/K/V [b,h,l,d] (device-side global refs)
                const int part = col >> 10;
                float* dst = (part == 0) ? g_Q : ((part == 1) ? g_K : g_V);
                const int within = col & 1023;
                const int hh2 = within >> 6, dd = within & 63;
#pragma unroll
                for (int rr = 0; rr < 2; rr++) {
                    const int m  = rbase + rr * 8;
                    const int bb = m >> 11, l = m & (SEQ_L - 1);
                    *(float2*)&dst[(((size_t)(bb * NUM_HEADS + hh2)) * SEQ_L + l) * HEAD_DIM + dd] =
                        rr ? v1 : v0;
                }
            } else {
                *(float2*)&Cout[(size_t)rbase * Ndim + col] = v0;
                *(float2*)&Cout[(size_t)(rbase + 8) * Ndim + col] = v1;
            }
        }
    }
}

// ================= PROVEN fp32 flash attention ===========================
#define BR 64
#define BC 64
#define QSTR 68
#define VSTR 64
#define FLASH_SMEM ((HEAD_DIM * QSTR * 2 + BC * VSTR + BC * QSTR) * 4)

__global__ __launch_bounds__(256, 2) void flash_kernel()
{
    extern __shared__ float sh[];
    float* Qs = sh;
    float* Ks = Qs + HEAD_DIM * QSTR;
    float* Vs = Ks + HEAD_DIM * QSTR;
    float* Ps = Vs + BC * VSTR;

    const int tid = threadIdx.x;
    const int tx  = tid & 15;
    const int ty  = tid >> 4;
    const int q0  = blockIdx.x * BR;
    const int bh  = blockIdx.y;

    const float* Qg = g_Q + ((size_t)bh * SEQ_L + q0) * HEAD_DIM;
    const float* Kg = g_K + (size_t)bh * SEQ_L * HEAD_DIM;
    const float* Vg = g_V + (size_t)bh * SEQ_L * HEAD_DIM;

#pragma unroll
    for (int p = 0; p < 4; p++) {
        const int u  = tid + p * 256;
        const int r  = u >> 4;
        const int d4 = (u & 15) << 2;
        float4 g = *(const float4*)(Qg + r * HEAD_DIM + d4);
        Qs[(d4 + 0) * QSTR + r] = g.x;
        Qs[(d4 + 1) * QSTR + r] = g.y;
        Qs[(d4 + 2) * QSTR + r] = g.z;
        Qs[(d4 + 3) * QSTR + r] = g.w;
    }

    float o[4][4];
    float mrun[4], lrun[4];
#pragma unroll
    for (int i = 0; i < 4; i++) {
        mrun[i] = -1e30f; lrun[i] = 0.f;
#pragma unroll
        for (int j = 0; j < 4; j++) o[i][j] = 0.f;
    }

    for (int kt = 0; kt < SEQ_L; kt += BC) {
#pragma unroll
        for (int p = 0; p < 4; p++) {
            const int u  = tid + p * 256;
            const int cc = u >> 4;
            const int d4 = (u & 15) << 2;
            float4 gk = *(const float4*)(Kg + (size_t)(kt + cc) * HEAD_DIM + d4);
            Ks[(d4 + 0) * QSTR + cc] = gk.x;
            Ks[(d4 + 1) * QSTR + cc] = gk.y;
            Ks[(d4 + 2) * QSTR + cc] = gk.z;
            Ks[(d4 + 3) * QSTR + cc] = gk.w;
            float4 gv = *(const float4*)(Vg + (size_t)(kt + cc) * HEAD_DIM + d4);
            *(float4*)&Vs[cc * VSTR + d4] = gv;
        }
        __syncthreads();

        float s[4][4];
#pragma unroll
        for (int i = 0; i < 4; i++)
#pragma unroll
            for (int j = 0; j < 4; j++) s[i][j] = 0.f;

#pragma unroll
        for (int d = 0; d < HEAD_DIM; d++) {
            float4 qa = *(const float4*)&Qs[d * QSTR + ty * 4];
            float4 ka = *(const float4*)&Ks[d * QSTR + tx * 4];
            float qv[4] = {qa.x, qa.y, qa.z, qa.w};
            float kv[4] = {ka.x, ka.y, ka.z, ka.w};
#pragma unroll
            for (int i = 0; i < 4; i++)
#pragma unroll
                for (int j = 0; j < 4; j++)
                    s[i][j] = fmaf(qv[i], kv[j], s[i][j]);
        }

#pragma unroll
        for (int i = 0; i < 4; i++) {
#pragma unroll
            for (int j = 0; j < 4; j++) s[i][j] *= 0.125f;

            float rm = fmaxf(fmaxf(s[i][0], s[i][1]), fmaxf(s[i][2], s[i][3]));
            rm = fmaxf(rm, __shfl_xor_sync(0xffffffffu, rm, 1, 16));
            rm = fmaxf(rm, __shfl_xor_sync(0xffffffffu, rm, 2, 16));
            rm = fmaxf(rm, __shfl_xor_sync(0xffffffffu, rm, 4, 16));
            rm = fmaxf(rm, __shfl_xor_sync(0xffffffffu, rm, 8, 16));

            const float mn    = fmaxf(mrun[i], rm);
            const float alpha = __expf(mrun[i] - mn);
            mrun[i] = mn;

            float rs = 0.f;
#pragma unroll
            for (int j = 0; j < 4; j++) {
                const float pe = __expf(s[i][j] - mn);
                s[i][j] = pe;
                rs += pe;
            }
            rs += __shfl_xor_sync(0xffffffffu, rs, 1, 16);
            rs += __shfl_xor_sync(0xffffffffu, rs, 2, 16);
            rs += __shfl_xor_sync(0xffffffffu, rs, 4, 16);
            rs += __shfl_xor_sync(0xffffffffu, rs, 8, 16);

            lrun[i] = lrun[i] * alpha + rs;
#pragma unroll
            for (int j = 0; j < 4; j++) o[i][j] *= alpha;
        }

#pragma unroll
        for (int i = 0; i < 4; i++)
#pragma unroll
            for (int j = 0; j < 4; j++)
                Ps[(tx * 4 + j) * QSTR + (ty * 4 + i)] = s[i][j];
        __syncthreads();

#pragma unroll
        for (int cc = 0; cc < BC; cc++) {
            float4 pa = *(const float4*)&Ps[cc * QSTR + ty * 4];
            float4 va = *(const float4*)&Vs[cc * VSTR + tx * 4];
            float pv[4] = {pa.x, pa.y, pa.z, pa.w};
            float vv[4] = {va.x, va.y, va.z, va.w};
#pragma unroll
            for (int i = 0; i < 4; i++)
#pragma unroll
                for (int j = 0; j < 4; j++)
                    o[i][j] = fmaf(pv[i], vv[j], o[i][j]);
        }
        __syncthreads();
    }

    const int b = bh >> 4;
    const int h = bh & 15;
#pragma unroll
    for (int i = 0; i < 4; i++) {
        const float inv = 1.f / lrun[i];
        const int row = q0 + ty * 4 + i;
        float4 ov = make_float4(o[i][0] * inv, o[i][1] * inv, o[i][2] * inv, o[i][3] * inv);
        *(float4*)&g_Ctx[((size_t)(b * SEQ_L + row)) * D_MODEL + h * HEAD_DIM + tx * 4] = ov;
    }
}

// ---------------- launch (NO device globals as arguments!) ------------------
extern "C" void kernel_launch(void* const* d_in, const int* in_sizes, int n_in,
                              void* d_out, int out_size)
{
    (void)in_sizes; (void)n_in; (void)out_size;
    const float* x    = (const float*)d_in[0];
    const float* Wqkv = (const float*)d_in[1];
    const float* bqkv = (const float*)d_in[2];
    const float* Wout = (const float*)d_in[3];
    const float* bout = (const float*)d_in[4];
    float* out = (float*)d_out;

    cudaFuncSetAttribute(flash_kernel, cudaFuncAttributeMaxDynamicSharedMemorySize,
                         FLASH_SMEM);

    // QKV projection — HMMA, scatter epilogue (writes g_Q/g_K/g_V internally)
    gemm_hmma<0><<<dim3(3 * D_MODEL / 128, M_TOK / 128), 256>>>(
        x, Wqkv, bqkv, nullptr, 3 * D_MODEL);

    // attention — proven fp32 flash (g_Q/g_K/g_V -> g_Ctx internally)
    flash_kernel<<<dim3(SEQ_L / BR, BATCH * NUM_HEADS), 256, FLASH_SMEM>>>();

    // output projection — HMMA, reads g_Ctx internally, writes harness out
    gemm_hmma<1><<<dim3(D_MODEL / 128, M_TOK / 128), 256>>>(
        nullptr, Wout, bout, out, D_MODEL);
}

// round 13
// speedup vs baseline: 2.1644x; 1.7500x over previous
#include <cuda_runtime.h>
#include <cuda_fp16.h>
#include <stdint.h>
#include <math.h>

#define NUM_HEADS 16
#define HEAD_DIM  64
#define SEQ_L     2048
#define BATCH     2
#define EMB_D     1024
#define D_MODEL   1024
#define KDIM      1024
#define M_TOK     (BATCH * SEQ_L)   // 4096

// ---------------- scratch (device globals: no allocation allowed) ----------
// RULE (learned R4-R11): device globals may ONLY be referenced inside device
// code. NEVER pass them as kernel arguments from host code.
__device__ __align__(16) float g_Q[(size_t)BATCH * NUM_HEADS * SEQ_L * HEAD_DIM];
__device__ __align__(16) float g_K[(size_t)BATCH * NUM_HEADS * SEQ_L * HEAD_DIM];
__device__ __align__(16) float g_V[(size_t)BATCH * NUM_HEADS * SEQ_L * HEAD_DIM];
__device__ __align__(16) float g_Ctx[(size_t)M_TOK * D_MODEL];

// ---------------- helpers ----------------
__device__ __forceinline__ void mma_f16(float* c, const uint32_t* a,
                                        uint32_t b0, uint32_t b1) {
    asm volatile(
        "mma.sync.aligned.m16n8k16.row.col.f32.f16.f16.f32 "
        "{%0,%1,%2,%3}, {%4,%5,%6,%7}, {%8,%9}, {%0,%1,%2,%3};"
        : "+f"(c[0]), "+f"(c[1]), "+f"(c[2]), "+f"(c[3])
        : "r"(a[0]), "r"(a[1]), "r"(a[2]), "r"(a[3]), "r"(b0), "r"(b1));
}
__device__ __forceinline__ uint32_t packh2(float x, float y) {
    __half2 t = __floats2half2_rn(x, y);   // .x = x = low half
    return *(uint32_t*)&t;
}
__device__ __forceinline__ void split4(float4 f, __half* hi, __half* lo) {
    hi[0] = __float2half_rn(f.x); lo[0] = __float2half_rn(f.x - __half2float(hi[0]));
    hi[1] = __float2half_rn(f.y); lo[1] = __float2half_rn(f.y - __half2float(hi[1]));
    hi[2] = __float2half_rn(f.z); lo[2] = __float2half_rn(f.z - __half2float(hi[2]));
    hi[3] = __float2half_rn(f.w); lo[3] = __float2half_rn(f.w - __half2float(hi[3]));
}

// ========== HMMA GEMM (R12-passing, UNCHANGED) ==============================
#define BKH  32
#define TSTR 40

template <int EPI>
__global__ __launch_bounds__(256) void gemm_hmma(
    const float* __restrict__ Ain,
    const float* __restrict__ W,
    const float* __restrict__ bias,
    float* __restrict__ Cout,
    int Ndim)
{
    __shared__ __align__(16) __half sm[4][128 * TSTR];

    const float* A = (EPI == 1) ? (const float*)g_Ctx : Ain;

    const int tid  = threadIdx.x;
    const int wid  = tid >> 5, lane = tid & 31;
    const int wm   = wid & 3;
    const int wn   = wid >> 2;
    const int g    = lane >> 2;
    const int tig  = lane & 3;
    const int rowBase = blockIdx.y * 128;
    const int colBase = blockIdx.x * 128;

    const int lrow = tid >> 1;
    const int lc   = (tid & 1) * 16;
    const int bn   = tid >> 1;
    const int bkh  = (tid & 1) * 16;

    const float* ap = A + (size_t)(rowBase + lrow) * KDIM + lc;
    const float* wp = W + (size_t)bkh * Ndim + colBase + bn;

    float acc[2][8][4];
#pragma unroll
    for (int mi = 0; mi < 2; mi++)
#pragma unroll
        for (int nf = 0; nf < 8; nf++)
#pragma unroll
            for (int q = 0; q < 4; q++) acc[mi][nf][q] = 0.f;

    for (int ch = 0; ch < KDIM / BKH; ch++) {
        float av[16], bv[16];
        const size_t ka = (size_t)ch * BKH;
#pragma unroll
        for (int q = 0; q < 4; q++)
            *(float4*)&av[q * 4] = *(const float4*)(ap + ka + q * 4);
#pragma unroll
        for (int q = 0; q < 16; q++)
            bv[q] = wp[(ka + q) * (size_t)Ndim];
        __syncthreads();

        __align__(16) __half hh[16], ll[16];
#pragma unroll
        for (int j = 0; j < 16; j++) {
            __half h = __float2half_rn(av[j]);
            hh[j] = h;
            ll[j] = __float2half_rn(av[j] - __half2float(h));
        }
        *(uint4*)&sm[0][lrow * TSTR + lc]     = *(uint4*)&hh[0];
        *(uint4*)&sm[0][lrow * TSTR + lc + 8] = *(uint4*)&hh[8];
        *(uint4*)&sm[1][lrow * TSTR + lc]     = *(uint4*)&ll[0];
        *(uint4*)&sm[1][lrow * TSTR + lc + 8] = *(uint4*)&ll[8];

#pragma unroll
        for (int j = 0; j < 16; j++) {
            __half h = __float2half_rn(bv[j]);
            hh[j] = h;
            ll[j] = __float2half_rn(bv[j] - __half2float(h));
        }
        *(uint4*)&sm[2][bn * TSTR + bkh]     = *(uint4*)&hh[0];
        *(uint4*)&sm[2][bn * TSTR + bkh + 8] = *(uint4*)&hh[8];
        *(uint4*)&sm[3][bn * TSTR + bkh]     = *(uint4*)&ll[0];
        *(uint4*)&sm[3][bn * TSTR + bkh + 8] = *(uint4*)&ll[8];
        __syncthreads();

#pragma unroll
        for (int ks = 0; ks < 2; ks++) {
            const int kb = ks * 16 + tig * 2;
            uint32_t ah[2][4], al[2][4];
#pragma unroll
            for (int mi = 0; mi < 2; mi++) {
                const int r = wm * 32 + mi * 16 + g;
                ah[mi][0] = *(const uint32_t*)&sm[0][r * TSTR + kb];
                ah[mi][1] = *(const uint32_t*)&sm[0][(r + 8) * TSTR + kb];
                ah[mi][2] = *(const uint32_t*)&sm[0][r * TSTR + kb + 8];
                ah[mi][3] = *(const uint32_t*)&sm[0][(r + 8) * TSTR + kb + 8];
                al[mi][0] = *(const uint32_t*)&sm[1][r * TSTR + kb];
                al[mi][1] = *(const uint32_t*)&sm[1][(r + 8) * TSTR + kb];
                al[mi][2] = *(const uint32_t*)&sm[1][r * TSTR + kb + 8];
                al[mi][3] = *(const uint32_t*)&sm[1][(r + 8) * TSTR + kb + 8];
            }
#pragma unroll
            for (int nf = 0; nf < 8; nf++) {
                const int n = wn * 64 + nf * 8 + g;
                const uint32_t bh0 = *(const uint32_t*)&sm[2][n * TSTR + kb];
                const uint32_t bh1 = *(const uint32_t*)&sm[2][n * TSTR + kb + 8];
                const uint32_t bl0 = *(const uint32_t*)&sm[3][n * TSTR + kb];
                const uint32_t bl1 = *(const uint32_t*)&sm[3][n * TSTR + kb + 8];
#pragma unroll
                for (int mi = 0; mi < 2; mi++) {
                    mma_f16(acc[mi][nf], ah[mi], bh0, bh1);
                    mma_f16(acc[mi][nf], ah[mi], bl0, bl1);
                    mma_f16(acc[mi][nf], al[mi], bh0, bh1);
                }
            }
        }
    }

#pragma unroll
    for (int mi = 0; mi < 2; mi++) {
        const int rbase = rowBase + wm * 32 + mi * 16 + g;
#pragma unroll
        for (int nf = 0; nf < 8; nf++) {
            const int col = colBase + wn * 64 + nf * 8 + 2 * tig;
            const float bx = __ldg(bias + col), by = __ldg(bias + col + 1);
            float2 v0 = make_float2(acc[mi][nf][0] + bx, acc[mi][nf][1] + by);
            float2 v1 = make_float2(acc[mi][nf][2] + bx, acc[mi][nf][3] + by);
            if (EPI == 0) {
                const int part = col >> 10;
                float* dst = (part == 0) ? g_Q : ((part == 1) ? g_K : g_V);
                const int within = col & 1023;
                const int hh2 = within >> 6, dd = within & 63;
#pragma unroll
                for (int rr = 0; rr < 2; rr++) {
                    const int m  = rbase + rr * 8;
                    const int bb = m >> 11, l = m & (SEQ_L - 1);
                    *(float2*)&dst[(((size_t)(bb * NUM_HEADS + hh2)) * SEQ_L + l) * HEAD_DIM + dd] =
                        rr ? v1 : v0;
                }
            } else {
                *(float2*)&Cout[(size_t)rbase * Ndim + col] = v0;
                *(float2*)&Cout[(size_t)(rbase + 8) * Ndim + col] = v1;
            }
        }
    }
}

// ========== NEW: HMMA flash attention =======================================
// Br=128 (8 warps x m16 band), Bc=64, D=64.  Q A-frags in registers (hi/lo,
// pre-scaled 1/8).  K,V staged fp16 hi/lo in smem.  S = 3-pass split,
// P fp16 (register C->A repack), O += P@V with V hi/lo 2-pass.
#define KVSTR 72   // smem row stride in halves; B-frag loads conflict-free

__global__ __launch_bounds__(256) void flash_hmma()
{
    __shared__ __align__(16) __half Ksh[64 * KVSTR], Ksl[64 * KVSTR],
                                    Vsh[64 * KVSTR], Vsl[64 * KVSTR];

    const int tid = threadIdx.x, wid = tid >> 5, lane = tid & 31;
    const int g = lane >> 2, tig = lane & 3;
    const int q0 = blockIdx.x * 128;
    const int bh = blockIdx.y;
    const int b = bh >> 4, h = bh & 15;

    const float* Qg = g_Q + (size_t)bh * SEQ_L * HEAD_DIM;
    const float* Kg = g_K + (size_t)bh * SEQ_L * HEAD_DIM;
    const float* Vg = g_V + (size_t)bh * SEQ_L * HEAD_DIM;

    // ---- Q A-fragments (rows r0, r0+8), scaled by 1/sqrt(64), hi/lo split ----
    uint32_t qh[4][4], ql[4][4];
    const int r0 = q0 + wid * 16 + g;
#pragma unroll
    for (int ks = 0; ks < 4; ks++) {
#pragma unroll
        for (int kk = 0; kk < 2; kk++) {
#pragma unroll
            for (int rr = 0; rr < 2; rr++) {
                float2 f = *(const float2*)&Qg[(size_t)(r0 + rr * 8) * HEAD_DIM
                                               + ks * 16 + kk * 8 + 2 * tig];
                f.x *= 0.125f; f.y *= 0.125f;
                __half hx = __float2half_rn(f.x), hy = __float2half_rn(f.y);
                __half lx = __float2half_rn(f.x - __half2float(hx));
                __half ly = __float2half_rn(f.y - __half2float(hy));
                __half2 ph; ph.x = hx; ph.y = hy;
                __half2 pl; pl.x = lx; pl.y = ly;
                qh[ks][kk * 2 + rr] = *(uint32_t*)&ph;
                ql[ks][kk * 2 + rr] = *(uint32_t*)&pl;
            }
        }
    }

    float m0 = -1e30f, m1 = -1e30f, l0 = 0.f, l1 = 0.f;
    float oa[8][4];
#pragma unroll
    for (int nf = 0; nf < 8; nf++)
#pragma unroll
        for (int q = 0; q < 4; q++) oa[nf][q] = 0.f;

    for (int kt = 0; kt < SEQ_L; kt += 64) {
        __syncthreads();   // previous chunk fully consumed
        // ---- stage K, V chunk (fp16 hi/lo) ----
#pragma unroll
        for (int p = 0; p < 4; p++) {
            const int u   = tid + p * 256;
            const int tok = u >> 4;
            const int d4  = (u & 15) * 4;
            float4 kf = *(const float4*)&Kg[(size_t)(kt + tok) * HEAD_DIM + d4];
            float4 vf = *(const float4*)&Vg[(size_t)(kt + tok) * HEAD_DIM + d4];
            __align__(8) __half khh[4], kll[4], vhh[4], vll[4];
            split4(kf, khh, kll);
            split4(vf, vhh, vll);
            *(uint2*)&Ksh[tok * KVSTR + d4] = *(uint2*)khh;
            *(uint2*)&Ksl[tok * KVSTR + d4] = *(uint2*)kll;
            *(uint2*)&Vsh[tok * KVSTR + d4] = *(uint2*)vhh;
            *(uint2*)&Vsl[tok * KVSTR + d4] = *(uint2*)vll;
        }
        __syncthreads();

        // ---- S = Q @ K^T, 3-pass split, fp32 acc ----
        float sa[8][4];
#pragma unroll
        for (int nf = 0; nf < 8; nf++)
#pragma unroll
            for (int q = 0; q < 4; q++) sa[nf][q] = 0.f;

#pragma unroll
        for (int kc = 0; kc < 4; kc++) {
            const int kb = kc * 16 + tig * 2;
#pragma unroll
            for (int nf = 0; nf < 8; nf++) {
                const int n = nf * 8 + g;
                const uint32_t b0 = *(const uint32_t*)&Ksh[n * KVSTR + kb];
                const uint32_t b1 = *(const uint32_t*)&Ksh[n * KVSTR + kb + 8];
                const uint32_t c0 = *(const uint32_t*)&Ksl[n * KVSTR + kb];
                const uint32_t c1 = *(const uint32_t*)&Ksl[n * KVSTR + kb + 8];
                mma_f16(sa[nf], qh[kc], b0, b1);   // QhKh
                mma_f16(sa[nf], qh[kc], c0, c1);   // QhKl
                mma_f16(sa[nf], ql[kc], b0, b1);   // QlKh
            }
        }

        // ---- online softmax (rows g and g+8; reduce over 4-lane tig group) ----
        float rm0 = -1e30f, rm1 = -1e30f;
#pragma unroll
        for (int nf = 0; nf < 8; nf++) {
            rm0 = fmaxf(rm0, fmaxf(sa[nf][0], sa[nf][1]));
            rm1 = fmaxf(rm1, fmaxf(sa[nf][2], sa[nf][3]));
        }
        rm0 = fmaxf(rm0, __shfl_xor_sync(0xffffffffu, rm0, 1));
        rm0 = fmaxf(rm0, __shfl_xor_sync(0xffffffffu, rm0, 2));
        rm1 = fmaxf(rm1, __shfl_xor_sync(0xffffffffu, rm1, 1));
        rm1 = fmaxf(rm1, __shfl_xor_sync(0xffffffffu, rm1, 2));

        const float mn0 = fmaxf(m0, rm0), mn1 = fmaxf(m1, rm1);
        const float a0 = __expf(m0 - mn0), a1 = __expf(m1 - mn1);
        m0 = mn0; m1 = mn1;

        float rs0 = 0.f, rs1 = 0.f;
#pragma unroll
        for (int nf = 0; nf < 8; nf++) {
            sa[nf][0] = __expf(sa[nf][0] - mn0); rs0 += sa[nf][0];
            sa[nf][1] = __expf(sa[nf][1] - mn0); rs0 += sa[nf][1];
            sa[nf][2] = __expf(sa[nf][2] - mn1); rs1 += sa[nf][2];
            sa[nf][3] = __expf(sa[nf][3] - mn1); rs1 += sa[nf][3];
        }
        rs0 += __shfl_xor_sync(0xffffffffu, rs0, 1);
        rs0 += __shfl_xor_sync(0xffffffffu, rs0, 2);
        rs1 += __shfl_xor_sync(0xffffffffu, rs1, 1);
        rs1 += __shfl_xor_sync(0xffffffffu, rs1, 2);

        l0 = l0 * a0 + rs0;
        l1 = l1 * a1 + rs1;
#pragma unroll
        for (int nf = 0; nf < 8; nf++) {
            oa[nf][0] *= a0; oa[nf][1] *= a0;
            oa[nf][2] *= a1; oa[nf][3] *= a1;
        }

        // ---- P: C-layout -> A-layout register repack (fp16) ----
        uint32_t pa[4][4];
#pragma unroll
        for (int ks = 0; ks < 4; ks++) {
            pa[ks][0] = packh2(sa[2 * ks][0],     sa[2 * ks][1]);
            pa[ks][1] = packh2(sa[2 * ks][2],     sa[2 * ks][3]);
            pa[ks][2] = packh2(sa[2 * ks + 1][0], sa[2 * ks + 1][1]);
            pa[ks][3] = packh2(sa[2 * ks + 1][2], sa[2 * ks + 1][3]);
        }

        // ---- O += P @ V (V hi/lo, 2-pass) ----
#pragma unroll
        for (int kc = 0; kc < 4; kc++) {
            const int t0 = kc * 16 + 2 * tig;
#pragma unroll
            for (int nf = 0; nf < 8; nf++) {
                const int n = nf * 8 + g;
                const uint32_t v0 =
                    (uint32_t)*(const unsigned short*)&Vsh[t0 * KVSTR + n] |
                    ((uint32_t)*(const unsigned short*)&Vsh[(t0 + 1) * KVSTR + n] << 16);
                const uint32_t v1 =
                    (uint32_t)*(const unsigned short*)&Vsh[(t0 + 8) * KVSTR + n] |
                    ((uint32_t)*(const unsigned short*)&Vsh[(t0 + 9) * KVSTR + n] << 16);
                mma_f16(oa[nf], pa[kc], v0, v1);
                const uint32_t w0 =
                    (uint32_t)*(const unsigned short*)&Vsl[t0 * KVSTR + n] |
                    ((uint32_t)*(const unsigned short*)&Vsl[(t0 + 1) * KVSTR + n] << 16);
                const uint32_t w1 =
                    (uint32_t)*(const unsigned short*)&Vsl[(t0 + 8) * KVSTR + n] |
                    ((uint32_t)*(const unsigned short*)&Vsl[(t0 + 9) * KVSTR + n] << 16);
                mma_f16(oa[nf], pa[kc], w0, w1);
            }
        }
    }

    // ---- epilogue: normalize, write ctx [b,l,h*64+d] ----
    const float i0 = 1.f / l0, i1 = 1.f / l1;
    float* C0 = &g_Ctx[((size_t)(b * SEQ_L + r0)) * D_MODEL + h * HEAD_DIM];
    float* C1 = C0 + 8 * D_MODEL;
#pragma unroll
    for (int nf = 0; nf < 8; nf++) {
        const int col = nf * 8 + 2 * tig;
        *(float2*)&C0[col] = make_float2(oa[nf][0] * i0, oa[nf][1] * i0);
        *(float2*)&C1[col] = make_float2(oa[nf][2] * i1, oa[nf][3] * i1);
    }
}

// ---------------- launch (NO device globals as arguments!) ------------------
extern "C" void kernel_launch(void* const* d_in, const int* in_sizes, int n_in,
                              void* d_out, int out_size)
{
    (void)in_sizes; (void)n_in; (void)out_size;
    const float* x    = (const float*)d_in[0];
    const float* Wqkv = (const float*)d_in[1];
    const float* bqkv = (const float*)d_in[2];
    const float* Wout = (const float*)d_in[3];
    const float* bout = (const float*)d_in[4];
    float* out = (float*)d_out;

    // QKV projection — HMMA, scatter epilogue (writes g_Q/g_K/g_V internally)
    gemm_hmma<0><<<dim3(3 * D_MODEL / 128, M_TOK / 128), 256>>>(
        x, Wqkv, bqkv, nullptr, 3 * D_MODEL);

    // attention — HMMA flash (g_Q/g_K/g_V -> g_Ctx internally)
    flash_hmma<<<dim3(SEQ_L / 128, BATCH * NUM_HEADS), 256>>>();

    // output projection — HMMA, reads g_Ctx internally, writes harness out
    gemm_hmma<1><<<dim3(D_MODEL / 128, M_TOK / 128), 256>>>(
        nullptr, Wout, bout, out, D_MODEL);
}

// round 14
// speedup vs baseline: 2.5102x; 1.1598x over previous
#include <cuda_runtime.h>
#include <cuda_fp16.h>
#include <stdint.h>
#include <math.h>

#define NUM_HEADS 16
#define HEAD_DIM  64
#define SEQ_L     2048
#define BATCH     2
#define EMB_D     1024
#define D_MODEL   1024
#define KDIM      1024
#define M_TOK     (BATCH * SEQ_L)   // 4096

// ---------------- scratch (device globals: no allocation allowed) ----------
// RULE (learned R4-R11): device globals may ONLY be referenced inside device
// code. NEVER pass them as kernel arguments from host code.
__device__ __align__(16) float g_Q[(size_t)BATCH * NUM_HEADS * SEQ_L * HEAD_DIM];
__device__ __align__(16) float g_K[(size_t)BATCH * NUM_HEADS * SEQ_L * HEAD_DIM];
__device__ __align__(16) float g_V[(size_t)BATCH * NUM_HEADS * SEQ_L * HEAD_DIM];
__device__ __align__(16) float g_Ctx[(size_t)M_TOK * D_MODEL];

// ---------------- helpers ----------------
__device__ __forceinline__ void mma_f16(float* c, const uint32_t* a,
                                        uint32_t b0, uint32_t b1) {
    asm volatile(
        "mma.sync.aligned.m16n8k16.row.col.f32.f16.f16.f32 "
        "{%0,%1,%2,%3}, {%4,%5,%6,%7}, {%8,%9}, {%0,%1,%2,%3};"
        : "+f"(c[0]), "+f"(c[1]), "+f"(c[2]), "+f"(c[3])
        : "r"(a[0]), "r"(a[1]), "r"(a[2]), "r"(a[3]), "r"(b0), "r"(b1));
}
__device__ __forceinline__ uint32_t packh2(float x, float y) {
    __half2 t = __floats2half2_rn(x, y);   // .x = x = low half
    return *(uint32_t*)&t;
}
__device__ __forceinline__ void split4(float4 f, __half* hi, __half* lo) {
    hi[0] = __float2half_rn(f.x); lo[0] = __float2half_rn(f.x - __half2float(hi[0]));
    hi[1] = __float2half_rn(f.y); lo[1] = __float2half_rn(f.y - __half2float(hi[1]));
    hi[2] = __float2half_rn(f.z); lo[2] = __float2half_rn(f.z - __half2float(hi[2]));
    hi[3] = __float2half_rn(f.w); lo[3] = __float2half_rn(f.w - __half2float(hi[3]));
}

// ========== HMMA GEMM (R12 core; NEW: 2 CTAs/SM via launch bounds) ==========
#define BKH  32
#define TSTR 40

template <int EPI>
__global__ __launch_bounds__(256, 2) void gemm_hmma(
    const float* __restrict__ Ain,
    const float* __restrict__ W,
    const float* __restrict__ bias,
    float* __restrict__ Cout,
    int Ndim)
{
    __shared__ __align__(16) __half sm[4][128 * TSTR];

    const float* A = (EPI == 1) ? (const float*)g_Ctx : Ain;

    const int tid  = threadIdx.x;
    const int wid  = tid >> 5, lane = tid & 31;
    const int wm   = wid & 3;
    const int wn   = wid >> 2;
    const int g    = lane >> 2;
    const int tig  = lane & 3;
    const int rowBase = blockIdx.y * 128;
    const int colBase = blockIdx.x * 128;

    const int lrow = tid >> 1;
    const int lc   = (tid & 1) * 16;
    const int bn   = tid >> 1;
    const int bkh  = (tid & 1) * 16;

    const float* ap = A + (size_t)(rowBase + lrow) * KDIM + lc;
    const float* wp = W + (size_t)bkh * Ndim + colBase + bn;

    float acc[2][8][4];
#pragma unroll
    for (int mi = 0; mi < 2; mi++)
#pragma unroll
        for (int nf = 0; nf < 8; nf++)
#pragma unroll
            for (int q = 0; q < 4; q++) acc[mi][nf][q] = 0.f;

    for (int ch = 0; ch < KDIM / BKH; ch++) {
        float av[16], bv[16];
        const size_t ka = (size_t)ch * BKH;
#pragma unroll
        for (int q = 0; q < 4; q++)
            *(float4*)&av[q * 4] = *(const float4*)(ap + ka + q * 4);
#pragma unroll
        for (int q = 0; q < 16; q++)
            bv[q] = wp[(ka + q) * (size_t)Ndim];
        __syncthreads();

        __align__(16) __half hh[16], ll[16];
#pragma unroll
        for (int j = 0; j < 16; j++) {
            __half h = __float2half_rn(av[j]);
            hh[j] = h;
            ll[j] = __float2half_rn(av[j] - __half2float(h));
        }
        *(uint4*)&sm[0][lrow * TSTR + lc]     = *(uint4*)&hh[0];
        *(uint4*)&sm[0][lrow * TSTR + lc + 8] = *(uint4*)&hh[8];
        *(uint4*)&sm[1][lrow * TSTR + lc]     = *(uint4*)&ll[0];
        *(uint4*)&sm[1][lrow * TSTR + lc + 8] = *(uint4*)&ll[8];

#pragma unroll
        for (int j = 0; j < 16; j++) {
            __half h = __float2half_rn(bv[j]);
            hh[j] = h;
            ll[j] = __float2half_rn(bv[j] - __half2float(h));
        }
        *(uint4*)&sm[2][bn * TSTR + bkh]     = *(uint4*)&hh[0];
        *(uint4*)&sm[2][bn * TSTR + bkh + 8] = *(uint4*)&hh[8];
        *(uint4*)&sm[3][bn * TSTR + bkh]     = *(uint4*)&ll[0];
        *(uint4*)&sm[3][bn * TSTR + bkh + 8] = *(uint4*)&ll[8];
        __syncthreads();

#pragma unroll
        for (int ks = 0; ks < 2; ks++) {
            const int kb = ks * 16 + tig * 2;
            uint32_t ah[2][4], al[2][4];
#pragma unroll
            for (int mi = 0; mi < 2; mi++) {
                const int r = wm * 32 + mi * 16 + g;
                ah[mi][0] = *(const uint32_t*)&sm[0][r * TSTR + kb];
                ah[mi][1] = *(const uint32_t*)&sm[0][(r + 8) * TSTR + kb];
                ah[mi][2] = *(const uint32_t*)&sm[0][r * TSTR + kb + 8];
                ah[mi][3] = *(const uint32_t*)&sm[0][(r + 8) * TSTR + kb + 8];
                al[mi][0] = *(const uint32_t*)&sm[1][r * TSTR + kb];
                al[mi][1] = *(const uint32_t*)&sm[1][(r + 8) * TSTR + kb];
                al[mi][2] = *(const uint32_t*)&sm[1][r * TSTR + kb + 8];
                al[mi][3] = *(const uint32_t*)&sm[1][(r + 8) * TSTR + kb + 8];
            }
#pragma unroll
            for (int nf = 0; nf < 8; nf++) {
                const int n = wn * 64 + nf * 8 + g;
                const uint32_t bh0 = *(const uint32_t*)&sm[2][n * TSTR + kb];
                const uint32_t bh1 = *(const uint32_t*)&sm[2][n * TSTR + kb + 8];
                const uint32_t bl0 = *(const uint32_t*)&sm[3][n * TSTR + kb];
                const uint32_t bl1 = *(const uint32_t*)&sm[3][n * TSTR + kb + 8];
#pragma unroll
                for (int mi = 0; mi < 2; mi++) {
                    mma_f16(acc[mi][nf], ah[mi], bh0, bh1);
                    mma_f16(acc[mi][nf], ah[mi], bl0, bl1);
                    mma_f16(acc[mi][nf], al[mi], bh0, bh1);
                }
            }
        }
    }

#pragma unroll
    for (int mi = 0; mi < 2; mi++) {
        const int rbase = rowBase + wm * 32 + mi * 16 + g;
#pragma unroll
        for (int nf = 0; nf < 8; nf++) {
            const int col = colBase + wn * 64 + nf * 8 + 2 * tig;
            const float bx = __ldg(bias + col), by = __ldg(bias + col + 1);
            float2 v0 = make_float2(acc[mi][nf][0] + bx, acc[mi][nf][1] + by);
            float2 v1 = make_float2(acc[mi][nf][2] + bx, acc[mi][nf][3] + by);
            if (EPI == 0) {
                const int part = col >> 10;
                float* dst = (part == 0) ? g_Q : ((part == 1) ? g_K : g_V);
                const int within = col & 1023;
                const int hh2 = within >> 6, dd = within & 63;
#pragma unroll
                for (int rr = 0; rr < 2; rr++) {
                    const int m  = rbase + rr * 8;
                    const int bb = m >> 11, l = m & (SEQ_L - 1);
                    *(float2*)&dst[(((size_t)(bb * NUM_HEADS + hh2)) * SEQ_L + l) * HEAD_DIM + dd] =
                        rr ? v1 : v0;
                }
            } else {
                *(float2*)&Cout[(size_t)rbase * Ndim + col] = v0;
                *(float2*)&Cout[(size_t)(rbase + 8) * Ndim + col] = v1;
            }
        }
    }
}

// ========== HMMA flash attention (NEW: V single-pass fp16) ==================
// Br=128 (8 warps x m16 band), Bc=64, D=64.  Q A-frags in registers (hi/lo,
// pre-scaled 1/8).  K staged fp16 hi/lo, V staged fp16 hi only.
// S = 3-pass split, P fp16 (register C->A repack), O += P@Vh (1 pass).
#define KVSTR 72   // smem row stride in halves; B-frag loads conflict-free

__global__ __launch_bounds__(256) void flash_hmma()
{
    __shared__ __align__(16) __half Ksh[64 * KVSTR], Ksl[64 * KVSTR],
                                    Vsh[64 * KVSTR];

    const int tid = threadIdx.x, wid = tid >> 5, lane = tid & 31;
    const int g = lane >> 2, tig = lane & 3;
    const int q0 = blockIdx.x * 128;
    const int bh = blockIdx.y;
    const int b = bh >> 4, h = bh & 15;

    const float* Qg = g_Q + (size_t)bh * SEQ_L * HEAD_DIM;
    const float* Kg = g_K + (size_t)bh * SEQ_L * HEAD_DIM;
    const float* Vg = g_V + (size_t)bh * SEQ_L * HEAD_DIM;

    // ---- Q A-fragments (rows r0, r0+8), scaled by 1/sqrt(64), hi/lo split ----
    uint32_t qh[4][4], ql[4][4];
    const int r0 = q0 + wid * 16 + g;
#pragma unroll
    for (int ks = 0; ks < 4; ks++) {
#pragma unroll
        for (int kk = 0; kk < 2; kk++) {
#pragma unroll
            for (int rr = 0; rr < 2; rr++) {
                float2 f = *(const float2*)&Qg[(size_t)(r0 + rr * 8) * HEAD_DIM
                                               + ks * 16 + kk * 8 + 2 * tig];
                f.x *= 0.125f; f.y *= 0.125f;
                __half hx = __float2half_rn(f.x), hy = __float2half_rn(f.y);
                __half lx = __float2half_rn(f.x - __half2float(hx));
                __half ly = __float2half_rn(f.y - __half2float(hy));
                __half2 ph; ph.x = hx; ph.y = hy;
                __half2 pl; pl.x = lx; pl.y = ly;
                qh[ks][kk * 2 + rr] = *(uint32_t*)&ph;
                ql[ks][kk * 2 + rr] = *(uint32_t*)&pl;
            }
        }
    }

    float m0 = -1e30f, m1 = -1e30f, l0 = 0.f, l1 = 0.f;
    float oa[8][4];
#pragma unroll
    for (int nf = 0; nf < 8; nf++)
#pragma unroll
        for (int q = 0; q < 4; q++) oa[nf][q] = 0.f;

    for (int kt = 0; kt < SEQ_L; kt += 64) {
        __syncthreads();   // previous chunk fully consumed
        // ---- stage K (hi/lo), V (hi only) ----
#pragma unroll
        for (int p = 0; p < 4; p++) {
            const int u   = tid + p * 256;
            const int tok = u >> 4;
            const int d4  = (u & 15) * 4;
            float4 kf = *(const float4*)&Kg[(size_t)(kt + tok) * HEAD_DIM + d4];
            float4 vf = *(const float4*)&Vg[(size_t)(kt + tok) * HEAD_DIM + d4];
            __align__(8) __half khh[4], kll[4], vhh[4];
            split4(kf, khh, kll);
            vhh[0] = __float2half_rn(vf.x);
            vhh[1] = __float2half_rn(vf.y);
            vhh[2] = __float2half_rn(vf.z);
            vhh[3] = __float2half_rn(vf.w);
            *(uint2*)&Ksh[tok * KVSTR + d4] = *(uint2*)khh;
            *(uint2*)&Ksl[tok * KVSTR + d4] = *(uint2*)kll;
            *(uint2*)&Vsh[tok * KVSTR + d4] = *(uint2*)vhh;
        }
        __syncthreads();

        // ---- S = Q @ K^T, 3-pass split, fp32 acc ----
        float sa[8][4];
#pragma unroll
        for (int nf = 0; nf < 8; nf++)
#pragma unroll
            for (int q = 0; q < 4; q++) sa[nf][q] = 0.f;

#pragma unroll
        for (int kc = 0; kc < 4; kc++) {
            const int kb = kc * 16 + tig * 2;
#pragma unroll
            for (int nf = 0; nf < 8; nf++) {
                const int n = nf * 8 + g;
                const uint32_t b0 = *(const uint32_t*)&Ksh[n * KVSTR + kb];
                const uint32_t b1 = *(const uint32_t*)&Ksh[n * KVSTR + kb + 8];
                const uint32_t c0 = *(const uint32_t*)&Ksl[n * KVSTR + kb];
                const uint32_t c1 = *(const uint32_t*)&Ksl[n * KVSTR + kb + 8];
                mma_f16(sa[nf], qh[kc], b0, b1);   // QhKh
                mma_f16(sa[nf], qh[kc], c0, c1);   // QhKl
                mma_f16(sa[nf], ql[kc], b0, b1);   // QlKh
            }
        }

        // ---- online softmax (rows g and g+8; reduce over 4-lane tig group) ----
        float rm0 = -1e30f, rm1 = -1e30f;
#pragma unroll
        for (int nf = 0; nf < 8; nf++) {
            rm0 = fmaxf(rm0, fmaxf(sa[nf][0], sa[nf][1]));
            rm1 = fmaxf(rm1, fmaxf(sa[nf][2], sa[nf][3]));
        }
        rm0 = fmaxf(rm0, __shfl_xor_sync(0xffffffffu, rm0, 1));
        rm0 = fmaxf(rm0, __shfl_xor_sync(0xffffffffu, rm0, 2));
        rm1 = fmaxf(rm1, __shfl_xor_sync(0xffffffffu, rm1, 1));
        rm1 = fmaxf(rm1, __shfl_xor_sync(0xffffffffu, rm1, 2));

        const float mn0 = fmaxf(m0, rm0), mn1 = fmaxf(m1, rm1);
        const float a0 = __expf(m0 - mn0), a1 = __expf(m1 - mn1);
        m0 = mn0; m1 = mn1;

        float rs0 = 0.f, rs1 = 0.f;
#pragma unroll
        for (int nf = 0; nf < 8; nf++) {
            sa[nf][0] = __expf(sa[nf][0] - mn0); rs0 += sa[nf][0];
            sa[nf][1] = __expf(sa[nf][1] - mn0); rs0 += sa[nf][1];
            sa[nf][2] = __expf(sa[nf][2] - mn1); rs1 += sa[nf][2];
            sa[nf][3] = __expf(sa[nf][3] - mn1); rs1 += sa[nf][3];
        }
        rs0 += __shfl_xor_sync(0xffffffffu, rs0, 1);
        rs0 += __shfl_xor_sync(0xffffffffu, rs0, 2);
        rs1 += __shfl_xor_sync(0xffffffffu, rs1, 1);
        rs1 += __shfl_xor_sync(0xffffffffu, rs1, 2);

        l0 = l0 * a0 + rs0;
        l1 = l1 * a1 + rs1;
#pragma unroll
        for (int nf = 0; nf < 8; nf++) {
            oa[nf][0] *= a0; oa[nf][1] *= a0;
            oa[nf][2] *= a1; oa[nf][3] *= a1;
        }

        // ---- P: C-layout -> A-layout register repack (fp16) ----
        uint32_t pa[4][4];
#pragma unroll
        for (int ks = 0; ks < 4; ks++) {
            pa[ks][0] = packh2(sa[2 * ks][0],     sa[2 * ks][1]);
            pa[ks][1] = packh2(sa[2 * ks][2],     sa[2 * ks][3]);
            pa[ks][2] = packh2(sa[2 * ks + 1][0], sa[2 * ks + 1][1]);
            pa[ks][3] = packh2(sa[2 * ks + 1][2], sa[2 * ks + 1][3]);
        }

        // ---- O += P @ Vh (single pass) ----
#pragma unroll
        for (int kc = 0; kc < 4; kc++) {
            const int t0 = kc * 16 + 2 * tig;
#pragma unroll
            for (int nf = 0; nf < 8; nf++) {
                const int n = nf * 8 + g;
                const uint32_t v0 =
                    (uint32_t)*(const unsigned short*)&Vsh[t0 * KVSTR + n] |
                    ((uint32_t)*(const unsigned short*)&Vsh[(t0 + 1) * KVSTR + n] << 16);
                const uint32_t v1 =
                    (uint32_t)*(const unsigned short*)&Vsh[(t0 + 8) * KVSTR + n] |
                    ((uint32_t)*(const unsigned short*)&Vsh[(t0 + 9) * KVSTR + n] << 16);
                mma_f16(oa[nf], pa[kc], v0, v1);
            }
        }
    }

    // ---- epilogue: normalize, write ctx [b,l,h*64+d] ----
    const float i0 = 1.f / l0, i1 = 1.f / l1;
    float* C0 = &g_Ctx[((size_t)(b * SEQ_L + r0)) * D_MODEL + h * HEAD_DIM];
    float* C1 = C0 + 8 * D_MODEL;
#pragma unroll
    for (int nf = 0; nf < 8; nf++) {
        const int col = nf * 8 + 2 * tig;
        *(float2*)&C0[col] = make_float2(oa[nf][0] * i0, oa[nf][1] * i0);
        *(float2*)&C1[col] = make_float2(oa[nf][2] * i1, oa[nf][3] * i1);
    }
}

// ---------------- launch (NO device globals as arguments!) ------------------
extern "C" void kernel_launch(void* const* d_in, const int* in_sizes, int n_in,
                              void* d_out, int out_size)
{
    (void)in_sizes; (void)n_in; (void)out_size;
    const float* x    = (const float*)d_in[0];
    const float* Wqkv = (const float*)d_in[1];
    const float* bqkv = (const float*)d_in[2];
    const float* Wout = (const float*)d_in[3];
    const float* bout = (const float*)d_in[4];
    float* out = (float*)d_out;

    // QKV projection — HMMA, scatter epilogue (writes g_Q/g_K/g_V internally)
    gemm_hmma<0><<<dim3(3 * D_MODEL / 128, M_TOK / 128), 256>>>(
        x, Wqkv, bqkv, nullptr, 3 * D_MODEL);

    // attention — HMMA flash (g_Q/g_K/g_V -> g_Ctx internally)
    flash_hmma<<<dim3(SEQ_L / 128, BATCH * NUM_HEADS), 256>>>();

    // output projection — HMMA, reads g_Ctx internally, writes harness out
    gemm_hmma<1><<<dim3(D_MODEL / 128, M_TOK / 128), 256>>>(
        nullptr, Wout, bout, out, D_MODEL);
}

// round 15
// speedup vs baseline: 2.6670x; 1.0625x over previous
#include <cuda_runtime.h>
#include <cuda_fp16.h>
#include <stdint.h>
#include <math.h>

#define NUM_HEADS 16
#define HEAD_DIM  64
#define SEQ_L     2048
#define BATCH     2
#define EMB_D     1024
#define D_MODEL   1024
#define KDIM      1024
#define M_TOK     (BATCH * SEQ_L)   // 4096

// ---------------- scratch (device globals: no allocation allowed) ----------
// RULE (learned R4-R11): device globals may ONLY be referenced inside device
// code. NEVER pass them as kernel arguments from host code.
__device__ __align__(16) float g_Q[(size_t)BATCH * NUM_HEADS * SEQ_L * HEAD_DIM];
__device__ __align__(16) float g_K[(size_t)BATCH * NUM_HEADS * SEQ_L * HEAD_DIM];
__device__ __align__(16) float g_V[(size_t)BATCH * NUM_HEADS * SEQ_L * HEAD_DIM];
__device__ __align__(16) float g_Ctx[(size_t)M_TOK * D_MODEL];

// ---------------- helpers ----------------
__device__ __forceinline__ void mma_f16(float* c, const uint32_t* a,
                                        uint32_t b0, uint32_t b1) {
    asm volatile(
        "mma.sync.aligned.m16n8k16.row.col.f32.f16.f16.f32 "
        "{%0,%1,%2,%3}, {%4,%5,%6,%7}, {%8,%9}, {%0,%1,%2,%3};"
        : "+f"(c[0]), "+f"(c[1]), "+f"(c[2]), "+f"(c[3])
        : "r"(a[0]), "r"(a[1]), "r"(a[2]), "r"(a[3]), "r"(b0), "r"(b1));
}
__device__ __forceinline__ uint32_t packh2(float x, float y) {
    __half2 t = __floats2half2_rn(x, y);   // .x = x = low half
    return *(uint32_t*)&t;
}
__device__ __forceinline__ void split4(float4 f, __half* hi, __half* lo) {
    hi[0] = __float2half_rn(f.x); lo[0] = __float2half_rn(f.x - __half2float(hi[0]));
    hi[1] = __float2half_rn(f.y); lo[1] = __float2half_rn(f.y - __half2float(hi[1]));
    hi[2] = __float2half_rn(f.z); lo[2] = __float2half_rn(f.z - __half2float(hi[2]));
    hi[3] = __float2half_rn(f.w); lo[3] = __float2half_rn(f.w - __half2float(hi[3]));
}

// ========== HMMA GEMM (NEW: software-pipelined register prefetch) ===========
#define BKH  32
#define TSTR 40

template <int EPI>
__global__ __launch_bounds__(256, 2) void gemm_hmma(
    const float* __restrict__ Ain,
    const float* __restrict__ W,
    const float* __restrict__ bias,
    float* __restrict__ Cout,
    int Ndim)
{
    __shared__ __align__(16) __half sm[4][128 * TSTR];

    const float* A = (EPI == 1) ? (const float*)g_Ctx : Ain;

    const int tid  = threadIdx.x;
    const int wid  = tid >> 5, lane = tid & 31;
    const int wm   = wid & 3;
    const int wn   = wid >> 2;
    const int g    = lane >> 2;
    const int tig  = lane & 3;
    const int rowBase = blockIdx.y * 128;
    const int colBase = blockIdx.x * 128;

    const int lrow = tid >> 1;
    const int lc   = (tid & 1) * 16;
    const int bn   = tid >> 1;
    const int bkh  = (tid & 1) * 16;

    const float* ap = A + (size_t)(rowBase + lrow) * KDIM + lc;
    const float* wp = W + (size_t)bkh * Ndim + colBase + bn;

    float acc[2][8][4];
#pragma unroll
    for (int mi = 0; mi < 2; mi++)
#pragma unroll
        for (int nf = 0; nf < 8; nf++)
#pragma unroll
            for (int q = 0; q < 4; q++) acc[mi][nf][q] = 0.f;

    const int NCH = KDIM / BKH;   // 32
    float av[16], bv[16];

    // prologue: load chunk 0
#pragma unroll
    for (int q = 0; q < 4; q++)
        *(float4*)&av[q * 4] = *(const float4*)(ap + q * 4);
#pragma unroll
    for (int q = 0; q < 16; q++)
        bv[q] = wp[(size_t)q * Ndim];

    for (int ch = 0; ch < NCH; ch++) {
        __syncthreads();   // previous chunk's smem fully consumed

        // stage current chunk (av/bv) into smem, hi/lo split
        __align__(16) __half hh[16], ll[16];
#pragma unroll
        for (int j = 0; j < 16; j++) {
            __half h = __float2half_rn(av[j]);
            hh[j] = h;
            ll[j] = __float2half_rn(av[j] - __half2float(h));
        }
        *(uint4*)&sm[0][lrow * TSTR + lc]     = *(uint4*)&hh[0];
        *(uint4*)&sm[0][lrow * TSTR + lc + 8] = *(uint4*)&hh[8];
        *(uint4*)&sm[1][lrow * TSTR + lc]     = *(uint4*)&ll[0];
        *(uint4*)&sm[1][lrow * TSTR + lc + 8] = *(uint4*)&ll[8];

#pragma unroll
        for (int j = 0; j < 16; j++) {
            __half h = __float2half_rn(bv[j]);
            hh[j] = h;
            ll[j] = __float2half_rn(bv[j] - __half2float(h));
        }
        *(uint4*)&sm[2][bn * TSTR + bkh]     = *(uint4*)&hh[0];
        *(uint4*)&sm[2][bn * TSTR + bkh + 8] = *(uint4*)&hh[8];
        *(uint4*)&sm[3][bn * TSTR + bkh]     = *(uint4*)&ll[0];
        *(uint4*)&sm[3][bn * TSTR + bkh + 8] = *(uint4*)&ll[8];
        __syncthreads();

        // prefetch NEXT chunk into (now dead) av/bv — LDG hides under MMAs
        if (ch + 1 < NCH) {
            const size_t ka = (size_t)(ch + 1) * BKH;
#pragma unroll
            for (int q = 0; q < 4; q++)
                *(float4*)&av[q * 4] = *(const float4*)(ap + ka + q * 4);
#pragma unroll
            for (int q = 0; q < 16; q++)
                bv[q] = wp[(ka + q) * (size_t)Ndim];
        }

        // compute current chunk from smem
#pragma unroll
        for (int ks = 0; ks < 2; ks++) {
            const int kb = ks * 16 + tig * 2;
            uint32_t ah[2][4], al[2][4];
#pragma unroll
            for (int mi = 0; mi < 2; mi++) {
                const int r = wm * 32 + mi * 16 + g;
                ah[mi][0] = *(const uint32_t*)&sm[0][r * TSTR + kb];
                ah[mi][1] = *(const uint32_t*)&sm[0][(r + 8) * TSTR + kb];
                ah[mi][2] = *(const uint32_t*)&sm[0][r * TSTR + kb + 8];
                ah[mi][3] = *(const uint32_t*)&sm[0][(r + 8) * TSTR + kb + 8];
                al[mi][0] = *(const uint32_t*)&sm[1][r * TSTR + kb];
                al[mi][1] = *(const uint32_t*)&sm[1][(r + 8) * TSTR + kb];
                al[mi][2] = *(const uint32_t*)&sm[1][r * TSTR + kb + 8];
                al[mi][3] = *(const uint32_t*)&sm[1][(r + 8) * TSTR + kb + 8];
            }
#pragma unroll
            for (int nf = 0; nf < 8; nf++) {
                const int n = wn * 64 + nf * 8 + g;
                const uint32_t bh0 = *(const uint32_t*)&sm[2][n * TSTR + kb];
                const uint32_t bh1 = *(const uint32_t*)&sm[2][n * TSTR + kb + 8];
                const uint32_t bl0 = *(const uint32_t*)&sm[3][n * TSTR + kb];
                const uint32_t bl1 = *(const uint32_t*)&sm[3][n * TSTR + kb + 8];
#pragma unroll
                for (int mi = 0; mi < 2; mi++) {
                    mma_f16(acc[mi][nf], ah[mi], bh0, bh1);
                    mma_f16(acc[mi][nf], ah[mi], bl0, bl1);
                    mma_f16(acc[mi][nf], al[mi], bh0, bh1);
                }
            }
        }
    }

#pragma unroll
    for (int mi = 0; mi < 2; mi++) {
        const int rbase = rowBase + wm * 32 + mi * 16 + g;
#pragma unroll
        for (int nf = 0; nf < 8; nf++) {
            const int col = colBase + wn * 64 + nf * 8 + 2 * tig;
            const float bx = __ldg(bias + col), by = __ldg(bias + col + 1);
            float2 v0 = make_float2(acc[mi][nf][0] + bx, acc[mi][nf][1] + by);
            float2 v1 = make_float2(acc[mi][nf][2] + bx, acc[mi][nf][3] + by);
            if (EPI == 0) {
                const int part = col >> 10;
                float* dst = (part == 0) ? g_Q : ((part == 1) ? g_K : g_V);
                const int within = col & 1023;
                const int hh2 = within >> 6, dd = within & 63;
#pragma unroll
                for (int rr = 0; rr < 2; rr++) {
                    const int m  = rbase + rr * 8;
                    const int bb = m >> 11, l = m & (SEQ_L - 1);
                    *(float2*)&dst[(((size_t)(bb * NUM_HEADS + hh2)) * SEQ_L + l) * HEAD_DIM + dd] =
                        rr ? v1 : v0;
                }
            } else {
                *(float2*)&Cout[(size_t)rbase * Ndim + col] = v0;
                *(float2*)&Cout[(size_t)(rbase + 8) * Ndim + col] = v1;
            }
        }
    }
}

// ========== HMMA flash attention (NEW: 2-pass S, no K-lo) ===================
// Br=128 (8 warps x m16 band), Bc=64, D=64.  Q A-frags in registers (hi/lo,
// pre-scaled 1/8).  K,V staged fp16 (hi only).  S = QhKh + QlKh (2-pass),
// P fp16 (register C->A repack), O += P@Vh (1 pass).
#define KVSTR 72   // smem row stride in halves; B-frag loads conflict-free

__global__ __launch_bounds__(256) void flash_hmma()
{
    __shared__ __align__(16) __half Ksh[64 * KVSTR], Vsh[64 * KVSTR];

    const int tid = threadIdx.x, wid = tid >> 5, lane = tid & 31;
    const int g = lane >> 2, tig = lane & 3;
    const int q0 = blockIdx.x * 128;
    const int bh = blockIdx.y;
    const int b = bh >> 4, h = bh & 15;

    const float* Qg = g_Q + (size_t)bh * SEQ_L * HEAD_DIM;
    const float* Kg = g_K + (size_t)bh * SEQ_L * HEAD_DIM;
    const float* Vg = g_V + (size_t)bh * SEQ_L * HEAD_DIM;

    // ---- Q A-fragments (rows r0, r0+8), scaled by 1/sqrt(64), hi/lo split ----
    uint32_t qh[4][4], ql[4][4];
    const int r0 = q0 + wid * 16 + g;
#pragma unroll
    for (int ks = 0; ks < 4; ks++) {
#pragma unroll
        for (int kk = 0; kk < 2; kk++) {
#pragma unroll
            for (int rr = 0; rr < 2; rr++) {
                float2 f = *(const float2*)&Qg[(size_t)(r0 + rr * 8) * HEAD_DIM
                                               + ks * 16 + kk * 8 + 2 * tig];
                f.x *= 0.125f; f.y *= 0.125f;
                __half hx = __float2half_rn(f.x), hy = __float2half_rn(f.y);
                __half lx = __float2half_rn(f.x - __half2float(hx));
                __half ly = __float2half_rn(f.y - __half2float(hy));
                __half2 ph; ph.x = hx; ph.y = hy;
                __half2 pl; pl.x = lx; pl.y = ly;
                qh[ks][kk * 2 + rr] = *(uint32_t*)&ph;
                ql[ks][kk * 2 + rr] = *(uint32_t*)&pl;
            }
        }
    }

    float m0 = -1e30f, m1 = -1e30f, l0 = 0.f, l1 = 0.f;
    float oa[8][4];
#pragma unroll
    for (int nf = 0; nf < 8; nf++)
#pragma unroll
        for (int q = 0; q < 4; q++) oa[nf][q] = 0.f;

    for (int kt = 0; kt < SEQ_L; kt += 64) {
        __syncthreads();   // previous chunk fully consumed
        // ---- stage K, V (fp16 hi only) ----
#pragma unroll
        for (int p = 0; p < 4; p++) {
            const int u   = tid + p * 256;
            const int tok = u >> 4;
            const int d4  = (u & 15) * 4;
            float4 kf = *(const float4*)&Kg[(size_t)(kt + tok) * HEAD_DIM + d4];
            float4 vf = *(const float4*)&Vg[(size_t)(kt + tok) * HEAD_DIM + d4];
            __align__(8) __half khh[4], vhh[4];
            khh[0] = __float2half_rn(kf.x);
            khh[1] = __float2half_rn(kf.y);
            khh[2] = __float2half_rn(kf.z);
            khh[3] = __float2half_rn(kf.w);
            vhh[0] = __float2half_rn(vf.x);
            vhh[1] = __float2half_rn(vf.y);
            vhh[2] = __float2half_rn(vf.z);
            vhh[3] = __float2half_rn(vf.w);
            *(uint2*)&Ksh[tok * KVSTR + d4] = *(uint2*)khh;
            *(uint2*)&Vsh[tok * KVSTR + d4] = *(uint2*)vhh;
        }
        __syncthreads();

        // ---- S = Q @ Kh^T, 2-pass split (Qh + Ql), fp32 acc ----
        float sa[8][4];
#pragma unroll
        for (int nf = 0; nf < 8; nf++)
#pragma unroll
            for (int q = 0; q < 4; q++) sa[nf][q] = 0.f;

#pragma unroll
        for (int kc = 0; kc < 4; kc++) {
            const int kb = kc * 16 + tig * 2;
#pragma unroll
            for (int nf = 0; nf < 8; nf++) {
                const int n = nf * 8 + g;
                const uint32_t b0 = *(const uint32_t*)&Ksh[n * KVSTR + kb];
                const uint32_t b1 = *(const uint32_t*)&Ksh[n * KVSTR + kb + 8];
                mma_f16(sa[nf], qh[kc], b0, b1);   // QhKh
                mma_f16(sa[nf], ql[kc], b0, b1);   // QlKh
            }
        }

        // ---- online softmax (rows g and g+8; reduce over 4-lane tig group) ----
        float rm0 = -1e30f, rm1 = -1e30f;
#pragma unroll
        for (int nf = 0; nf < 8; nf++) {
            rm0 = fmaxf(rm0, fmaxf(sa[nf][0], sa[nf][1]));
            rm1 = fmaxf(rm1, fmaxf(sa[nf][2], sa[nf][3]));
        }
        rm0 = fmaxf(rm0, __shfl_xor_sync(0xffffffffu, rm0, 1));
        rm0 = fmaxf(rm0, __shfl_xor_sync(0xffffffffu, rm0, 2));
        rm1 = fmaxf(rm1, __shfl_xor_sync(0xffffffffu, rm1, 1));
        rm1 = fmaxf(rm1, __shfl_xor_sync(0xffffffffu, rm1, 2));

        const float mn0 = fmaxf(m0, rm0), mn1 = fmaxf(m1, rm1);
        const float a0 = __expf(m0 - mn0), a1 = __expf(m1 - mn1);
        m0 = mn0; m1 = mn1;

        float rs0 = 0.f, rs1 = 0.f;
#pragma unroll
        for (int nf = 0; nf < 8; nf++) {
            sa[nf][0] = __expf(sa[nf][0] - mn0); rs0 += sa[nf][0];
            sa[nf][1] = __expf(sa[nf][1] - mn0); rs0 += sa[nf][1];
            sa[nf][2] = __expf(sa[nf][2] - mn1); rs1 += sa[nf][2];
            sa[nf][3] = __expf(sa[nf][3] - mn1); rs1 += sa[nf][3];
        }
        rs0 += __shfl_xor_sync(0xffffffffu, rs0, 1);
        rs0 += __shfl_xor_sync(0xffffffffu, rs0, 2);
        rs1 += __shfl_xor_sync(0xffffffffu, rs1, 1);
        rs1 += __shfl_xor_sync(0xffffffffu, rs1, 2);

        l0 = l0 * a0 + rs0;
        l1 = l1 * a1 + rs1;
#pragma unroll
        for (int nf = 0; nf < 8; nf++) {
            oa[nf][0] *= a0; oa[nf][1] *= a0;
            oa[nf][2] *= a1; oa[nf][3] *= a1;
        }

        // ---- P: C-layout -> A-layout register repack (fp16) ----
        uint32_t pa[4][4];
#pragma unroll
        for (int ks = 0; ks < 4; ks++) {
            pa[ks][0] = packh2(sa[2 * ks][0],     sa[2 * ks][1]);
            pa[ks][1] = packh2(sa[2 * ks][2],     sa[2 * ks][3]);
            pa[ks][2] = packh2(sa[2 * ks + 1][0], sa[2 * ks + 1][1]);
            pa[ks][3] = packh2(sa[2 * ks + 1][2], sa[2 * ks + 1][3]);
        }

        // ---- O += P @ Vh (single pass) ----
#pragma unroll
        for (int kc = 0; kc < 4; kc++) {
            const int t0 = kc * 16 + 2 * tig;
#pragma unroll
            for (int nf = 0; nf < 8; nf++) {
                const int n = nf * 8 + g;
                const uint32_t v0 =
                    (uint32_t)*(const unsigned short*)&Vsh[t0 * KVSTR + n] |
                    ((uint32_t)*(const unsigned short*)&Vsh[(t0 + 1) * KVSTR + n] << 16);
                const uint32_t v1 =
                    (uint32_t)*(const unsigned short*)&Vsh[(t0 + 8) * KVSTR + n] |
                    ((uint32_t)*(const unsigned short*)&Vsh[(t0 + 9) * KVSTR + n] << 16);
                mma_f16(oa[nf], pa[kc], v0, v1);
            }
        }
    }

    // ---- epilogue: normalize, write ctx [b,l,h*64+d] ----
    const float i0 = 1.f / l0, i1 = 1.f / l1;
    float* C0 = &g_Ctx[((size_t)(b * SEQ_L + r0)) * D_MODEL + h * HEAD_DIM];
    float* C1 = C0 + 8 * D_MODEL;
#pragma unroll
    for (int nf = 0; nf < 8; nf++) {
        const int col = nf * 8 + 2 * tig;
        *(float2*)&C0[col] = make_float2(oa[nf][0] * i0, oa[nf][1] * i0);
        *(float2*)&C1[col] = make_float2(oa[nf][2] * i1, oa[nf][3] * i1);
    }
}

// ---------------- launch (NO device globals as arguments!) ------------------
extern "C" void kernel_launch(void* const* d_in, const int* in_sizes, int n_in,
                              void* d_out, int out_size)
{
    (void)in_sizes; (void)n_in; (void)out_size;
    const float* x    = (const float*)d_in[0];
    const float* Wqkv = (const float*)d_in[1];
    const float* bqkv = (const float*)d_in[2];
    const float* Wout = (const float*)d_in[3];
    const float* bout = (const float*)d_in[4];
    float* out = (float*)d_out;

    // QKV projection — HMMA, scatter epilogue (writes g_Q/g_K/g_V internally)
    gemm_hmma<0><<<dim3(3 * D_MODEL / 128, M_TOK / 128), 256>>>(
        x, Wqkv, bqkv, nullptr, 3 * D_MODEL);

    // attention — HMMA flash (g_Q/g_K/g_V -> g_Ctx internally)
    flash_hmma<<<dim3(SEQ_L / 128, BATCH * NUM_HEADS), 256>>>();

    // output projection — HMMA, reads g_Ctx internally, writes harness out
    gemm_hmma<1><<<dim3(D_MODEL / 128, M_TOK / 128), 256>>>(
        nullptr, Wout, bout, out, D_MODEL);
}

// round 16
// speedup vs baseline: 2.8126x; 1.0546x over previous
#include <cuda_runtime.h>
#include <cuda_fp16.h>
#include <stdint.h>
#include <math.h>

#define NUM_HEADS 16
#define HEAD_DIM  64
#define SEQ_L     2048
#define BATCH     2
#define EMB_D     1024
#define D_MODEL   1024
#define KDIM      1024
#define M_TOK     (BATCH * SEQ_L)   // 4096

// ---------------- scratch (device globals: no allocation allowed) ----------
// RULE (learned R4-R11): device globals may ONLY be referenced inside device
// code. NEVER pass them as kernel arguments from host code.
__device__ __align__(16) float g_Q[(size_t)BATCH * NUM_HEADS * SEQ_L * HEAD_DIM];
__device__ __align__(16) float g_K[(size_t)BATCH * NUM_HEADS * SEQ_L * HEAD_DIM];
__device__ __align__(16) float g_V[(size_t)BATCH * NUM_HEADS * SEQ_L * HEAD_DIM];
__device__ __align__(16) float g_Ctx[(size_t)M_TOK * D_MODEL];

// ---------------- helpers ----------------
__device__ __forceinline__ void mma_f16(float* c, const uint32_t* a,
                                        uint32_t b0, uint32_t b1) {
    asm volatile(
        "mma.sync.aligned.m16n8k16.row.col.f32.f16.f16.f32 "
        "{%0,%1,%2,%3}, {%4,%5,%6,%7}, {%8,%9}, {%0,%1,%2,%3};"
        : "+f"(c[0]), "+f"(c[1]), "+f"(c[2]), "+f"(c[3])
        : "r"(a[0]), "r"(a[1]), "r"(a[2]), "r"(a[3]), "r"(b0), "r"(b1));
}
__device__ __forceinline__ uint32_t packh2(float x, float y) {
    __half2 t = __floats2half2_rn(x, y);   // .x = x = low half
    return *(uint32_t*)&t;
}
__device__ __forceinline__ uint32_t smem_u32(const void* p) {
    uint32_t a;
    asm("{ .reg .u64 t; cvta.to.shared.u64 t, %1; cvt.u32.u64 %0, t; }"
        : "=r"(a) : "l"(p));
    return a;
}
__device__ __forceinline__ void ldmx4(uint32_t& r0, uint32_t& r1, uint32_t& r2,
                                      uint32_t& r3, uint32_t addr) {
    asm volatile("ldmatrix.sync.aligned.m8n8.x4.shared.b16 {%0,%1,%2,%3}, [%4];"
                 : "=r"(r0), "=r"(r1), "=r"(r2), "=r"(r3) : "r"(addr));
}
__device__ __forceinline__ void ldmx4t(uint32_t& r0, uint32_t& r1, uint32_t& r2,
                                       uint32_t& r3, uint32_t addr) {
    asm volatile("ldmatrix.sync.aligned.m8n8.x4.trans.shared.b16 {%0,%1,%2,%3}, [%4];"
                 : "=r"(r0), "=r"(r1), "=r"(r2), "=r"(r3) : "r"(addr));
}

// ========== HMMA GEMM (NEW: double-buffered smem, one sync per chunk) =======
#define BKH   32
#define TSTR  40
#define BUFE  (4 * 128 * TSTR)              // halves per buffer
#define GEMM_SMEM (2 * BUFE * 2)            // bytes: 81920

template <int EPI>
__global__ __launch_bounds__(256, 2) void gemm_hmma(
    const float* __restrict__ Ain,
    const float* __restrict__ W,
    const float* __restrict__ bias,
    float* __restrict__ Cout,
    int Ndim)
{
    extern __shared__ __align__(16) __half dsm[];

    const float* A = (EPI == 1) ? (const float*)g_Ctx : Ain;

    const int tid  = threadIdx.x;
    const int wid  = tid >> 5, lane = tid & 31;
    const int wm   = wid & 3;
    const int wn   = wid >> 2;
    const int g    = lane >> 2;
    const int tig  = lane & 3;
    const int rowBase = blockIdx.y * 128;
    const int colBase = blockIdx.x * 128;

    const int lrow = tid >> 1;
    const int lc   = (tid & 1) * 16;
    const int bn   = tid >> 1;
    const int bkh  = (tid & 1) * 16;

    const float* ap = A + (size_t)(rowBase + lrow) * KDIM + lc;
    const float* wp = W + (size_t)bkh * Ndim + colBase + bn;

    float acc[2][8][4];
#pragma unroll
    for (int mi = 0; mi < 2; mi++)
#pragma unroll
        for (int nf = 0; nf < 8; nf++)
#pragma unroll
            for (int q = 0; q < 4; q++) acc[mi][nf][q] = 0.f;

    const int NCH = KDIM / BKH;   // 32
    float av[16], bv[16];

    // stage helper: fp32 regs -> hi/lo fp16 smem buffer
    auto stage = [&](__half* buf) {
        __half* sA0 = buf;
        __half* sA1 = buf + 128 * TSTR;
        __half* sB0 = buf + 2 * 128 * TSTR;
        __half* sB1 = buf + 3 * 128 * TSTR;
        __align__(16) __half hh[16], ll[16];
#pragma unroll
        for (int j = 0; j < 16; j++) {
            __half h = __float2half_rn(av[j]);
            hh[j] = h;
            ll[j] = __float2half_rn(av[j] - __half2float(h));
        }
        *(uint4*)&sA0[lrow * TSTR + lc]     = *(uint4*)&hh[0];
        *(uint4*)&sA0[lrow * TSTR + lc + 8] = *(uint4*)&hh[8];
        *(uint4*)&sA1[lrow * TSTR + lc]     = *(uint4*)&ll[0];
        *(uint4*)&sA1[lrow * TSTR + lc + 8] = *(uint4*)&ll[8];
#pragma unroll
        for (int j = 0; j < 16; j++) {
            __half h = __float2half_rn(bv[j]);
            hh[j] = h;
            ll[j] = __float2half_rn(bv[j] - __half2float(h));
        }
        *(uint4*)&sB0[bn * TSTR + bkh]     = *(uint4*)&hh[0];
        *(uint4*)&sB0[bn * TSTR + bkh + 8] = *(uint4*)&hh[8];
        *(uint4*)&sB1[bn * TSTR + bkh]     = *(uint4*)&ll[0];
        *(uint4*)&sB1[bn * TSTR + bkh + 8] = *(uint4*)&ll[8];
    };

    // prologue: load chunk 0 and stage into buffer 0
#pragma unroll
    for (int q = 0; q < 4; q++)
        *(float4*)&av[q * 4] = *(const float4*)(ap + q * 4);
#pragma unroll
    for (int q = 0; q < 16; q++)
        bv[q] = wp[(size_t)q * Ndim];
    stage(dsm);

    for (int ch = 0; ch < NCH; ch++) {
        __syncthreads();   // buf[ch&1] staged; buf[(ch+1)&1] free (consumed ch-1)

        const __half* sA0 = dsm + (ch & 1) * BUFE;
        const __half* sA1 = sA0 + 128 * TSTR;
        const __half* sB0 = sA0 + 2 * 128 * TSTR;
        const __half* sB1 = sA0 + 3 * 128 * TSTR;

        // prefetch next chunk (LDG in flight under the MMAs below)
        if (ch + 1 < NCH) {
            const size_t ka = (size_t)(ch + 1) * BKH;
#pragma unroll
            for (int q = 0; q < 4; q++)
                *(float4*)&av[q * 4] = *(const float4*)(ap + ka + q * 4);
#pragma unroll
            for (int q = 0; q < 16; q++)
                bv[q] = wp[(ka + q) * (size_t)Ndim];
        }

        // compute current chunk
#pragma unroll
        for (int ks = 0; ks < 2; ks++) {
            const int kb = ks * 16 + tig * 2;
            uint32_t ah[2][4], al[2][4];
#pragma unroll
            for (int mi = 0; mi < 2; mi++) {
                const int r = wm * 32 + mi * 16 + g;
                ah[mi][0] = *(const uint32_t*)&sA0[r * TSTR + kb];
                ah[mi][1] = *(const uint32_t*)&sA0[(r + 8) * TSTR + kb];
                ah[mi][2] = *(const uint32_t*)&sA0[r * TSTR + kb + 8];
                ah[mi][3] = *(const uint32_t*)&sA0[(r + 8) * TSTR + kb + 8];
                al[mi][0] = *(const uint32_t*)&sA1[r * TSTR + kb];
                al[mi][1] = *(const uint32_t*)&sA1[(r + 8) * TSTR + kb];
                al[mi][2] = *(const uint32_t*)&sA1[r * TSTR + kb + 8];
                al[mi][3] = *(const uint32_t*)&sA1[(r + 8) * TSTR + kb + 8];
            }
#pragma unroll
            for (int nf = 0; nf < 8; nf++) {
                const int n = wn * 64 + nf * 8 + g;
                const uint32_t bh0 = *(const uint32_t*)&sB0[n * TSTR + kb];
                const uint32_t bh1 = *(const uint32_t*)&sB0[n * TSTR + kb + 8];
                const uint32_t bl0 = *(const uint32_t*)&sB1[n * TSTR + kb];
                const uint32_t bl1 = *(const uint32_t*)&sB1[n * TSTR + kb + 8];
#pragma unroll
                for (int mi = 0; mi < 2; mi++) {
                    mma_f16(acc[mi][nf], ah[mi], bh0, bh1);
                    mma_f16(acc[mi][nf], ah[mi], bl0, bl1);
                    mma_f16(acc[mi][nf], al[mi], bh0, bh1);
                }
            }
        }

        // stage next chunk into the other buffer (no sync needed here)
        if (ch + 1 < NCH)
            stage(dsm + ((ch + 1) & 1) * BUFE);
    }

#pragma unroll
    for (int mi = 0; mi < 2; mi++) {
        const int rbase = rowBase + wm * 32 + mi * 16 + g;
#pragma unroll
        for (int nf = 0; nf < 8; nf++) {
            const int col = colBase + wn * 64 + nf * 8 + 2 * tig;
            const float bx = __ldg(bias + col), by = __ldg(bias + col + 1);
            float2 v0 = make_float2(acc[mi][nf][0] + bx, acc[mi][nf][1] + by);
            float2 v1 = make_float2(acc[mi][nf][2] + bx, acc[mi][nf][3] + by);
            if (EPI == 0) {
                const int part = col >> 10;
                float* dst = (part == 0) ? g_Q : ((part == 1) ? g_K : g_V);
                const int within = col & 1023;
                const int hh2 = within >> 6, dd = within & 63;
#pragma unroll
                for (int rr = 0; rr < 2; rr++) {
                    const int m  = rbase + rr * 8;
                    const int bb = m >> 11, l = m & (SEQ_L - 1);
                    *(float2*)&dst[(((size_t)(bb * NUM_HEADS + hh2)) * SEQ_L + l) * HEAD_DIM + dd] =
                        rr ? v1 : v0;
                }
            } else {
                *(float2*)&Cout[(size_t)rbase * Ndim + col] = v0;
                *(float2*)&Cout[(size_t)(rbase + 8) * Ndim + col] = v1;
            }
        }
    }
}

// ========== HMMA flash attention (NEW: ldmatrix fragment loads) =============
// Br=128 (8 warps x m16 band), Bc=64, D=64.  Q A-frags in registers (hi/lo,
// pre-scaled 1/8).  K,V staged fp16.  S = QhKh + QlKh, P fp16 register
// repack, O += P@Vh.  K frags via ldmatrix.x4; V frags via ldmatrix.x4.trans
// (lane maps verified against the proven scalar constructions).
#define KVSTR 72   // smem row stride in halves; ldmatrix rows conflict-free

__global__ __launch_bounds__(256) void flash_hmma()
{
    __shared__ __align__(16) __half Ksh[64 * KVSTR], Vsh[64 * KVSTR];

    const int tid = threadIdx.x, wid = tid >> 5, lane = tid & 31;
    const int g = lane >> 2, tig = lane & 3;
    const int q0 = blockIdx.x * 128;
    const int bh = blockIdx.y;
    const int b = bh >> 4, h = bh & 15;

    const float* Qg = g_Q + (size_t)bh * SEQ_L * HEAD_DIM;
    const float* Kg = g_K + (size_t)bh * SEQ_L * HEAD_DIM;
    const float* Vg = g_V + (size_t)bh * SEQ_L * HEAD_DIM;

    // ldmatrix per-lane row/col components
    const int nkr = (lane & 7) + ((lane >> 4) & 1) * 8;  // K: n-row offset
    const int kko = ((lane >> 3) & 1) * 8;               // K: k-col offset
    const int vtr = (lane & 7) + ((lane >> 3) & 1) * 8;  // V: tok-row offset
    const int vno = ((lane >> 4) & 1) * 8;               // V: n-col offset
    const uint32_t kbase = smem_u32(Ksh);
    const uint32_t vbase = smem_u32(Vsh);

    // ---- Q A-fragments (rows r0, r0+8), scaled by 1/sqrt(64), hi/lo split ----
    uint32_t qh[4][4], ql[4][4];
    const int r0 = q0 + wid * 16 + g;
#pragma unroll
    for (int ks = 0; ks < 4; ks++) {
#pragma unroll
        for (int kk = 0; kk < 2; kk++) {
#pragma unroll
            for (int rr = 0; rr < 2; rr++) {
                float2 f = *(const float2*)&Qg[(size_t)(r0 + rr * 8) * HEAD_DIM
                                               + ks * 16 + kk * 8 + 2 * tig];
                f.x *= 0.125f; f.y *= 0.125f;
                __half hx = __float2half_rn(f.x), hy = __float2half_rn(f.y);
                __half lx = __float2half_rn(f.x - __half2float(hx));
                __half ly = __float2half_rn(f.y - __half2float(hy));
                __half2 ph; ph.x = hx; ph.y = hy;
                __half2 pl; pl.x = lx; pl.y = ly;
                qh[ks][kk * 2 + rr] = *(uint32_t*)&ph;
                ql[ks][kk * 2 + rr] = *(uint32_t*)&pl;
            }
        }
    }

    float m0 = -1e30f, m1 = -1e30f, l0 = 0.f, l1 = 0.f;
    float oa[8][4];
#pragma unroll
    for (int nf = 0; nf < 8; nf++)
#pragma unroll
        for (int q = 0; q < 4; q++) oa[nf][q] = 0.f;

    for (int kt = 0; kt < SEQ_L; kt += 64) {
        __syncthreads();   // previous chunk fully consumed
        // ---- stage K, V (fp16 hi only) ----
#pragma unroll
        for (int p = 0; p < 4; p++) {
            const int u   = tid + p * 256;
            const int tok = u >> 4;
            const int d4  = (u & 15) * 4;
            float4 kf = *(const float4*)&Kg[(size_t)(kt + tok) * HEAD_DIM + d4];
            float4 vf = *(const float4*)&Vg[(size_t)(kt + tok) * HEAD_DIM + d4];
            __align__(8) __half khh[4], vhh[4];
            khh[0] = __float2half_rn(kf.x);
            khh[1] = __float2half_rn(kf.y);
            khh[2] = __float2half_rn(kf.z);
            khh[3] = __float2half_rn(kf.w);
            vhh[0] = __float2half_rn(vf.x);
            vhh[1] = __float2half_rn(vf.y);
            vhh[2] = __float2half_rn(vf.z);
            vhh[3] = __float2half_rn(vf.w);
            *(uint2*)&Ksh[tok * KVSTR + d4] = *(uint2*)khh;
            *(uint2*)&Vsh[tok * KVSTR + d4] = *(uint2*)vhh;
        }
        __syncthreads();

        // ---- S = Q @ Kh^T, 2-pass split (Qh + Ql), fp32 acc ----
        float sa[8][4];
#pragma unroll
        for (int nf = 0; nf < 8; nf++)
#pragma unroll
            for (int q = 0; q < 4; q++) sa[nf][q] = 0.f;

#pragma unroll
        for (int kc = 0; kc < 4; kc++) {
#pragma unroll
            for (int nfp = 0; nfp < 4; nfp++) {
                uint32_t b0a, b1a, b0b, b1b;
                ldmx4(b0a, b1a, b0b, b1b,
                      kbase + (uint32_t)((nfp * 16 + nkr) * KVSTR + kc * 16 + kko) * 2);
                mma_f16(sa[2 * nfp],     qh[kc], b0a, b1a);
                mma_f16(sa[2 * nfp],     ql[kc], b0a, b1a);
                mma_f16(sa[2 * nfp + 1], qh[kc], b0b, b1b);
                mma_f16(sa[2 * nfp + 1], ql[kc], b0b, b1b);
            }
        }

        // ---- online softmax (rows g and g+8; reduce over 4-lane tig group) ----
        float rm0 = -1e30f, rm1 = -1e30f;
#pragma unroll
        for (int nf = 0; nf < 8; nf++) {
            rm0 = fmaxf(rm0, fmaxf(sa[nf][0], sa[nf][1]));
            rm1 = fmaxf(rm1, fmaxf(sa[nf][2], sa[nf][3]));
        }
        rm0 = fmaxf(rm0, __shfl_xor_sync(0xffffffffu, rm0, 1));
        rm0 = fmaxf(rm0, __shfl_xor_sync(0xffffffffu, rm0, 2));
        rm1 = fmaxf(rm1, __shfl_xor_sync(0xffffffffu, rm1, 1));
        rm1 = fmaxf(rm1, __shfl_xor_sync(0xffffffffu, rm1, 2));

        const float mn0 = fmaxf(m0, rm0), mn1 = fmaxf(m1, rm1);
        const float a0 = __expf(m0 - mn0), a1 = __expf(m1 - mn1);
        m0 = mn0; m1 = mn1;

        float rs0 = 0.f, rs1 = 0.f;
#pragma unroll
        for (int nf = 0; nf < 8; nf++) {
            sa[nf][0] = __expf(sa[nf][0] - mn0); rs0 += sa[nf][0];
            sa[nf][1] = __expf(sa[nf][1] - mn0); rs0 += sa[nf][1];
            sa[nf][2] = __expf(sa[nf][2] - mn1); rs1 += sa[nf][2];
            sa[nf][3] = __expf(sa[nf][3] - mn1); rs1 += sa[nf][3];
        }
        rs0 += __shfl_xor_sync(0xffffffffu, rs0, 1);
        rs0 += __shfl_xor_sync(0xffffffffu, rs0, 2);
        rs1 += __shfl_xor_sync(0xffffffffu, rs1, 1);
        rs1 += __shfl_xor_sync(0xffffffffu, rs1, 2);

        l0 = l0 * a0 + rs0;
        l1 = l1 * a1 + rs1;
#pragma unroll
        for (int nf = 0; nf < 8; nf++) {
            oa[nf][0] *= a0; oa[nf][1] *= a0;
            oa[nf][2] *= a1; oa[nf][3] *= a1;
        }

        // ---- P: C-layout -> A-layout register repack (fp16) ----
        uint32_t pa[4][4];
#pragma unroll
        for (int ks = 0; ks < 4; ks++) {
            pa[ks][0] = packh2(sa[2 * ks][0],     sa[2 * ks][1]);
            pa[ks][1] = packh2(sa[2 * ks][2],     sa[2 * ks][3]);
            pa[ks][2] = packh2(sa[2 * ks + 1][0], sa[2 * ks + 1][1]);
            pa[ks][3] = packh2(sa[2 * ks + 1][2], sa[2 * ks + 1][3]);
        }

        // ---- O += P @ Vh (V frags via ldmatrix.trans) ----
#pragma unroll
        for (int kc = 0; kc < 4; kc++) {
#pragma unroll
            for (int nfp = 0; nfp < 4; nfp++) {
                uint32_t v0a, v1a, v0b, v1b;
                ldmx4t(v0a, v1a, v0b, v1b,
                       vbase + (uint32_t)((kc * 16 + vtr) * KVSTR + nfp * 16 + vno) * 2);
                mma_f16(oa[2 * nfp],     pa[kc], v0a, v1a);
                mma_f16(oa[2 * nfp + 1], pa[kc], v0b, v1b);
            }
        }
    }

    // ---- epilogue: normalize, write ctx [b,l,h*64+d] ----
    const float i0 = 1.f / l0, i1 = 1.f / l1;
    float* C0 = &g_Ctx[((size_t)(b * SEQ_L + r0)) * D_MODEL + h * HEAD_DIM];
    float* C1 = C0 + 8 * D_MODEL;
#pragma unroll
    for (int nf = 0; nf < 8; nf++) {
        const int col = nf * 8 + 2 * tig;
        *(float2*)&C0[col] = make_float2(oa[nf][0] * i0, oa[nf][1] * i0);
        *(float2*)&C1[col] = make_float2(oa[nf][2] * i1, oa[nf][3] * i1);
    }
}

// ---------------- launch (NO device globals as arguments!) ------------------
extern "C" void kernel_launch(void* const* d_in, const int* in_sizes, int n_in,
                              void* d_out, int out_size)
{
    (void)in_sizes; (void)n_in; (void)out_size;
    const float* x    = (const float*)d_in[0];
    const float* Wqkv = (const float*)d_in[1];
    const float* bqkv = (const float*)d_in[2];
    const float* Wout = (const float*)d_in[3];
    const float* bout = (const float*)d_in[4];
    float* out = (float*)d_out;

    // >48KB dynamic smem opt-in for both GEMM instantiations (idempotent)
    cudaFuncSetAttribute(gemm_hmma<0>, cudaFuncAttributeMaxDynamicSharedMemorySize,
                         GEMM_SMEM);
    cudaFuncSetAttribute(gemm_hmma<1>, cudaFuncAttributeMaxDynamicSharedMemorySize,
                         GEMM_SMEM);

    // QKV projection — HMMA double-buffered, scatter epilogue
    gemm_hmma<0><<<dim3(3 * D_MODEL / 128, M_TOK / 128), 256, GEMM_SMEM>>>(
        x, Wqkv, bqkv, nullptr, 3 * D_MODEL);

    // attention — HMMA flash with ldmatrix fragment loads
    flash_hmma<<<dim3(SEQ_L / 128, BATCH * NUM_HEADS), 256>>>();

    // output projection — HMMA double-buffered
    gemm_hmma<1><<<dim3(D_MODEL / 128, M_TOK / 128), 256, GEMM_SMEM>>>(
        nullptr, Wout, bout, out, D_MODEL);
}

// round 17
// speedup vs baseline: 3.0115x; 1.0707x over previous
#include <cuda_runtime.h>
#include <cuda_fp16.h>
#include <stdint.h>
#include <math.h>

#define NUM_HEADS 16
#define HEAD_DIM  64
#define SEQ_L     2048
#define BATCH     2
#define EMB_D     1024
#define D_MODEL   1024
#define KDIM      1024
#define M_TOK     (BATCH * SEQ_L)   // 4096

// ---------------- scratch (device globals: no allocation allowed) ----------
// RULE (learned R4-R11): device globals may ONLY be referenced inside device
// code. NEVER pass them as kernel arguments from host code.
__device__ __align__(16) float g_Q[(size_t)BATCH * NUM_HEADS * SEQ_L * HEAD_DIM];
__device__ __align__(16) float g_K[(size_t)BATCH * NUM_HEADS * SEQ_L * HEAD_DIM];
__device__ __align__(16) float g_V[(size_t)BATCH * NUM_HEADS * SEQ_L * HEAD_DIM];
__device__ __align__(16) float g_Ctx[(size_t)M_TOK * D_MODEL];

// ---------------- helpers ----------------
__device__ __forceinline__ void mma_f16(float* c, const uint32_t* a,
                                        uint32_t b0, uint32_t b1) {
    asm volatile(
        "mma.sync.aligned.m16n8k16.row.col.f32.f16.f16.f32 "
        "{%0,%1,%2,%3}, {%4,%5,%6,%7}, {%8,%9}, {%0,%1,%2,%3};"
        : "+f"(c[0]), "+f"(c[1]), "+f"(c[2]), "+f"(c[3])
        : "r"(a[0]), "r"(a[1]), "r"(a[2]), "r"(a[3]), "r"(b0), "r"(b1));
}
__device__ __forceinline__ uint32_t packh2(float x, float y) {
    __half2 t = __floats2half2_rn(x, y);   // .x = x = low half
    return *(uint32_t*)&t;
}
__device__ __forceinline__ uint32_t smem_u32(const void* p) {
    uint32_t a;
    asm("{ .reg .u64 t; cvta.to.shared.u64 t, %1; cvt.u32.u64 %0, t; }"
        : "=r"(a) : "l"(p));
    return a;
}
__device__ __forceinline__ void ldmx4(uint32_t& r0, uint32_t& r1, uint32_t& r2,
                                      uint32_t& r3, uint32_t addr) {
    asm volatile("ldmatrix.sync.aligned.m8n8.x4.shared.b16 {%0,%1,%2,%3}, [%4];"
                 : "=r"(r0), "=r"(r1), "=r"(r2), "=r"(r3) : "r"(addr));
}
__device__ __forceinline__ void ldmx4t(uint32_t& r0, uint32_t& r1, uint32_t& r2,
                                       uint32_t& r3, uint32_t addr) {
    asm volatile("ldmatrix.sync.aligned.m8n8.x4.trans.shared.b16 {%0,%1,%2,%3}, [%4];"
                 : "=r"(r0), "=r"(r1), "=r"(r2), "=r"(r3) : "r"(addr));
}

// ========== HMMA GEMM (NEW: ldmatrix fragment loads) ========================
#define BKH   32
#define TSTR  40
#define BUFE  (4 * 128 * TSTR)              // halves per buffer
#define GEMM_SMEM (2 * BUFE * 2)            // bytes: 81920

template <int EPI>
__global__ __launch_bounds__(256, 2) void gemm_hmma(
    const float* __restrict__ Ain,
    const float* __restrict__ W,
    const float* __restrict__ bias,
    float* __restrict__ Cout,
    int Ndim)
{
    extern __shared__ __align__(16) __half dsm[];

    const float* A = (EPI == 1) ? (const float*)g_Ctx : Ain;

    const int tid  = threadIdx.x;
    const int wid  = tid >> 5, lane = tid & 31;
    const int wm   = wid & 3;
    const int wn   = wid >> 2;
    const int g    = lane >> 2;
    const int tig  = lane & 3;
    const int rowBase = blockIdx.y * 128;
    const int colBase = blockIdx.x * 128;

    const int lrow = tid >> 1;
    const int lc   = (tid & 1) * 16;
    const int bn   = tid >> 1;
    const int bkh  = (tid & 1) * 16;

    // ldmatrix lane maps (B map proven in flash R16; A map per PTX spec)
    const int arow = (lane & 7) + ((lane >> 3) & 1) * 8;  // A: row offset
    const int acol = ((lane >> 4) & 1) * 8;               // A: k offset
    const int nkr  = (lane & 7) + ((lane >> 4) & 1) * 8;  // B: n offset
    const int kko  = ((lane >> 3) & 1) * 8;               // B: k offset

    const float* ap = A + (size_t)(rowBase + lrow) * KDIM + lc;
    const float* wp = W + (size_t)bkh * Ndim + colBase + bn;

    float acc[2][8][4];
#pragma unroll
    for (int mi = 0; mi < 2; mi++)
#pragma unroll
        for (int nf = 0; nf < 8; nf++)
#pragma unroll
            for (int q = 0; q < 4; q++) acc[mi][nf][q] = 0.f;

    const int NCH = KDIM / BKH;   // 32
    float av[16], bv[16];

    // stage helper: fp32 regs -> hi/lo fp16 smem buffer
    auto stage = [&](__half* buf) {
        __half* sA0 = buf;
        __half* sA1 = buf + 128 * TSTR;
        __half* sB0 = buf + 2 * 128 * TSTR;
        __half* sB1 = buf + 3 * 128 * TSTR;
        __align__(16) __half hh[16], ll[16];
#pragma unroll
        for (int j = 0; j < 16; j++) {
            __half h = __float2half_rn(av[j]);
            hh[j] = h;
            ll[j] = __float2half_rn(av[j] - __half2float(h));
        }
        *(uint4*)&sA0[lrow * TSTR + lc]     = *(uint4*)&hh[0];
        *(uint4*)&sA0[lrow * TSTR + lc + 8] = *(uint4*)&hh[8];
        *(uint4*)&sA1[lrow * TSTR + lc]     = *(uint4*)&ll[0];
        *(uint4*)&sA1[lrow * TSTR + lc + 8] = *(uint4*)&ll[8];
#pragma unroll
        for (int j = 0; j < 16; j++) {
            __half h = __float2half_rn(bv[j]);
            hh[j] = h;
            ll[j] = __float2half_rn(bv[j] - __half2float(h));
        }
        *(uint4*)&sB0[bn * TSTR + bkh]     = *(uint4*)&hh[0];
        *(uint4*)&sB0[bn * TSTR + bkh + 8] = *(uint4*)&hh[8];
        *(uint4*)&sB1[bn * TSTR + bkh]     = *(uint4*)&ll[0];
        *(uint4*)&sB1[bn * TSTR + bkh + 8] = *(uint4*)&ll[8];
    };

    // prologue: load chunk 0 and stage into buffer 0
#pragma unroll
    for (int q = 0; q < 4; q++)
        *(float4*)&av[q * 4] = *(const float4*)(ap + q * 4);
#pragma unroll
    for (int q = 0; q < 16; q++)
        bv[q] = wp[(size_t)q * Ndim];
    stage(dsm);

    for (int ch = 0; ch < NCH; ch++) {
        __syncthreads();   // buf[ch&1] staged; buf[(ch+1)&1] free (consumed ch-1)

        const uint32_t uA0 = smem_u32(dsm + (ch & 1) * BUFE);
        const uint32_t uA1 = uA0 + 128 * TSTR * 2;
        const uint32_t uB0 = uA0 + 2 * 128 * TSTR * 2;
        const uint32_t uB1 = uA0 + 3 * 128 * TSTR * 2;

        // prefetch next chunk (LDG in flight under the MMAs below)
        if (ch + 1 < NCH) {
            const size_t ka = (size_t)(ch + 1) * BKH;
#pragma unroll
            for (int q = 0; q < 4; q++)
                *(float4*)&av[q * 4] = *(const float4*)(ap + ka + q * 4);
#pragma unroll
            for (int q = 0; q < 16; q++)
                bv[q] = wp[(ka + q) * (size_t)Ndim];
        }

        // compute current chunk — all fragments via ldmatrix.x4
#pragma unroll
        for (int ks = 0; ks < 2; ks++) {
            uint32_t ah[2][4], al[2][4];
#pragma unroll
            for (int mi = 0; mi < 2; mi++) {
                const uint32_t ao =
                    (uint32_t)((wm * 32 + mi * 16 + arow) * TSTR + ks * 16 + acol) * 2;
                ldmx4(ah[mi][0], ah[mi][1], ah[mi][2], ah[mi][3], uA0 + ao);
                ldmx4(al[mi][0], al[mi][1], al[mi][2], al[mi][3], uA1 + ao);
            }
#pragma unroll
            for (int nfp = 0; nfp < 4; nfp++) {
                const uint32_t bo =
                    (uint32_t)((wn * 64 + nfp * 16 + nkr) * TSTR + ks * 16 + kko) * 2;
                uint32_t bh0a, bh1a, bh0b, bh1b, bl0a, bl1a, bl0b, bl1b;
                ldmx4(bh0a, bh1a, bh0b, bh1b, uB0 + bo);
                ldmx4(bl0a, bl1a, bl0b, bl1b, uB1 + bo);
#pragma unroll
                for (int mi = 0; mi < 2; mi++) {
                    mma_f16(acc[mi][2 * nfp],     ah[mi], bh0a, bh1a);
                    mma_f16(acc[mi][2 * nfp],     ah[mi], bl0a, bl1a);
                    mma_f16(acc[mi][2 * nfp],     al[mi], bh0a, bh1a);
                    mma_f16(acc[mi][2 * nfp + 1], ah[mi], bh0b, bh1b);
                    mma_f16(acc[mi][2 * nfp + 1], ah[mi], bl0b, bl1b);
                    mma_f16(acc[mi][2 * nfp + 1], al[mi], bh0b, bh1b);
                }
            }
        }

        // stage next chunk into the other buffer (no sync needed here)
        if (ch + 1 < NCH)
            stage(dsm + ((ch + 1) & 1) * BUFE);
    }

#pragma unroll
    for (int mi = 0; mi < 2; mi++) {
        const int rbase = rowBase + wm * 32 + mi * 16 + g;
#pragma unroll
        for (int nf = 0; nf < 8; nf++) {
            const int col = colBase + wn * 64 + nf * 8 + 2 * tig;
            const float bx = __ldg(bias + col), by = __ldg(bias + col + 1);
            float2 v0 = make_float2(acc[mi][nf][0] + bx, acc[mi][nf][1] + by);
            float2 v1 = make_float2(acc[mi][nf][2] + bx, acc[mi][nf][3] + by);
            if (EPI == 0) {
                const int part = col >> 10;
                float* dst = (part == 0) ? g_Q : ((part == 1) ? g_K : g_V);
                const int within = col & 1023;
                const int hh2 = within >> 6, dd = within & 63;
#pragma unroll
                for (int rr = 0; rr < 2; rr++) {
                    const int m  = rbase + rr * 8;
                    const int bb = m >> 11, l = m & (SEQ_L - 1);
                    *(float2*)&dst[(((size_t)(bb * NUM_HEADS + hh2)) * SEQ_L + l) * HEAD_DIM + dd] =
                        rr ? v1 : v0;
                }
            } else {
                *(float2*)&Cout[(size_t)rbase * Ndim + col] = v0;
                *(float2*)&Cout[(size_t)(rbase + 8) * Ndim + col] = v1;
            }
        }
    }
}

// ========== HMMA flash attention (R16-passing, UNCHANGED) ===================
#define KVSTR 72   // smem row stride in halves; ldmatrix rows conflict-free

__global__ __launch_bounds__(256) void flash_hmma()
{
    __shared__ __align__(16) __half Ksh[64 * KVSTR], Vsh[64 * KVSTR];

    const int tid = threadIdx.x, wid = tid >> 5, lane = tid & 31;
    const int g = lane >> 2, tig = lane & 3;
    const int q0 = blockIdx.x * 128;
    const int bh = blockIdx.y;
    const int b = bh >> 4, h = bh & 15;

    const float* Qg = g_Q + (size_t)bh * SEQ_L * HEAD_DIM;
    const float* Kg = g_K + (size_t)bh * SEQ_L * HEAD_DIM;
    const float* Vg = g_V + (size_t)bh * SEQ_L * HEAD_DIM;

    const int nkr = (lane & 7) + ((lane >> 4) & 1) * 8;  // K: n-row offset
    const int kko = ((lane >> 3) & 1) * 8;               // K: k-col offset
    const int vtr = (lane & 7) + ((lane >> 3) & 1) * 8;  // V: tok-row offset
    const int vno = ((lane >> 4) & 1) * 8;               // V: n-col offset
    const uint32_t kbase = smem_u32(Ksh);
    const uint32_t vbase = smem_u32(Vsh);

    uint32_t qh[4][4], ql[4][4];
    const int r0 = q0 + wid * 16 + g;
#pragma unroll
    for (int ks = 0; ks < 4; ks++) {
#pragma unroll
        for (int kk = 0; kk < 2; kk++) {
#pragma unroll
            for (int rr = 0; rr < 2; rr++) {
                float2 f = *(const float2*)&Qg[(size_t)(r0 + rr * 8) * HEAD_DIM
                                               + ks * 16 + kk * 8 + 2 * tig];
                f.x *= 0.125f; f.y *= 0.125f;
                __half hx = __float2half_rn(f.x), hy = __float2half_rn(f.y);
                __half lx = __float2half_rn(f.x - __half2float(hx));
                __half ly = __float2half_rn(f.y - __half2float(hy));
                __half2 ph; ph.x = hx; ph.y = hy;
                __half2 pl; pl.x = lx; pl.y = ly;
                qh[ks][kk * 2 + rr] = *(uint32_t*)&ph;
                ql[ks][kk * 2 + rr] = *(uint32_t*)&pl;
            }
        }
    }

    float m0 = -1e30f, m1 = -1e30f, l0 = 0.f, l1 = 0.f;
    float oa[8][4];
#pragma unroll
    for (int nf = 0; nf < 8; nf++)
#pragma unroll
        for (int q = 0; q < 4; q++) oa[nf][q] = 0.f;

    for (int kt = 0; kt < SEQ_L; kt += 64) {
        __syncthreads();
#pragma unroll
        for (int p = 0; p < 4; p++) {
            const int u   = tid + p * 256;
            const int tok = u >> 4;
            const int d4  = (u & 15) * 4;
            float4 kf = *(const float4*)&Kg[(size_t)(kt + tok) * HEAD_DIM + d4];
            float4 vf = *(const float4*)&Vg[(size_t)(kt + tok) * HEAD_DIM + d4];
            __align__(8) __half khh[4], vhh[4];
            khh[0] = __float2half_rn(kf.x);
            khh[1] = __float2half_rn(kf.y);
            khh[2] = __float2half_rn(kf.z);
            khh[3] = __float2half_rn(kf.w);
            vhh[0] = __float2half_rn(vf.x);
            vhh[1] = __float2half_rn(vf.y);
            vhh[2] = __float2half_rn(vf.z);
            vhh[3] = __float2half_rn(vf.w);
            *(uint2*)&Ksh[tok * KVSTR + d4] = *(uint2*)khh;
            *(uint2*)&Vsh[tok * KVSTR + d4] = *(uint2*)vhh;
        }
        __syncthreads();

        float sa[8][4];
#pragma unroll
        for (int nf = 0; nf < 8; nf++)
#pragma unroll
            for (int q = 0; q < 4; q++) sa[nf][q] = 0.f;

#pragma unroll
        for (int kc = 0; kc < 4; kc++) {
#pragma unroll
            for (int nfp = 0; nfp < 4; nfp++) {
                uint32_t b0a, b1a, b0b, b1b;
                ldmx4(b0a, b1a, b0b, b1b,
                      kbase + (uint32_t)((nfp * 16 + nkr) * KVSTR + kc * 16 + kko) * 2);
                mma_f16(sa[2 * nfp],     qh[kc], b0a, b1a);
                mma_f16(sa[2 * nfp],     ql[kc], b0a, b1a);
                mma_f16(sa[2 * nfp + 1], qh[kc], b0b, b1b);
                mma_f16(sa[2 * nfp + 1], ql[kc], b0b, b1b);
            }
        }

        float rm0 = -1e30f, rm1 = -1e30f;
#pragma unroll
        for (int nf = 0; nf < 8; nf++) {
            rm0 = fmaxf(rm0, fmaxf(sa[nf][0], sa[nf][1]));
            rm1 = fmaxf(rm1, fmaxf(sa[nf][2], sa[nf][3]));
        }
        rm0 = fmaxf(rm0, __shfl_xor_sync(0xffffffffu, rm0, 1));
        rm0 = fmaxf(rm0, __shfl_xor_sync(0xffffffffu, rm0, 2));
        rm1 = fmaxf(rm1, __shfl_xor_sync(0xffffffffu, rm1, 1));
        rm1 = fmaxf(rm1, __shfl_xor_sync(0xffffffffu, rm1, 2));

        const float mn0 = fmaxf(m0, rm0), mn1 = fmaxf(m1, rm1);
        const float a0 = __expf(m0 - mn0), a1 = __expf(m1 - mn1);
        m0 = mn0; m1 = mn1;

        float rs0 = 0.f, rs1 = 0.f;
#pragma unroll
        for (int nf = 0; nf < 8; nf++) {
            sa[nf][0] = __expf(sa[nf][0] - mn0); rs0 += sa[nf][0];
            sa[nf][1] = __expf(sa[nf][1] - mn0); rs0 += sa[nf][1];
            sa[nf][2] = __expf(sa[nf][2] - mn1); rs1 += sa[nf][2];
            sa[nf][3] = __expf(sa[nf][3] - mn1); rs1 += sa[nf][3];
        }
        rs0 += __shfl_xor_sync(0xffffffffu, rs0, 1);
        rs0 += __shfl_xor_sync(0xffffffffu, rs0, 2);
        rs1 += __shfl_xor_sync(0xffffffffu, rs1, 1);
        rs1 += __shfl_xor_sync(0xffffffffu, rs1, 2);

        l0 = l0 * a0 + rs0;
        l1 = l1 * a1 + rs1;
#pragma unroll
        for (int nf = 0; nf < 8; nf++) {
            oa[nf][0] *= a0; oa[nf][1] *= a0;
            oa[nf][2] *= a1; oa[nf][3] *= a1;
        }

        uint32_t pa[4][4];
#pragma unroll
        for (int ks = 0; ks < 4; ks++) {
            pa[ks][0] = packh2(sa[2 * ks][0],     sa[2 * ks][1]);
            pa[ks][1] = packh2(sa[2 * ks][2],     sa[2 * ks][3]);
            pa[ks][2] = packh2(sa[2 * ks + 1][0], sa[2 * ks + 1][1]);
            pa[ks][3] = packh2(sa[2 * ks + 1][2], sa[2 * ks + 1][3]);
        }

#pragma unroll
        for (int kc = 0; kc < 4; kc++) {
#pragma unroll
            for (int nfp = 0; nfp < 4; nfp++) {
                uint32_t v0a, v1a, v0b, v1b;
                ldmx4t(v0a, v1a, v0b, v1b,
                       vbase + (uint32_t)((kc * 16 + vtr) * KVSTR + nfp * 16 + vno) * 2);
                mma_f16(oa[2 * nfp],     pa[kc], v0a, v1a);
                mma_f16(oa[2 * nfp + 1], pa[kc], v0b, v1b);
            }
        }
    }

    const float i0 = 1.f / l0, i1 = 1.f / l1;
    float* C0 = &g_Ctx[((size_t)(b * SEQ_L + r0)) * D_MODEL + h * HEAD_DIM];
    float* C1 = C0 + 8 * D_MODEL;
#pragma unroll
    for (int nf = 0; nf < 8; nf++) {
        const int col = nf * 8 + 2 * tig;
        *(float2*)&C0[col] = make_float2(oa[nf][0] * i0, oa[nf][1] * i0);
        *(float2*)&C1[col] = make_float2(oa[nf][2] * i1, oa[nf][3] * i1);
    }
}

// ---------------- launch (NO device globals as arguments!) ------------------
extern "C" void kernel_launch(void* const* d_in, const int* in_sizes, int n_in,
                              void* d_out, int out_size)
{
    (void)in_sizes; (void)n_in; (void)out_size;
    const float* x    = (const float*)d_in[0];
    const float* Wqkv = (const float*)d_in[1];
    const float* bqkv = (const float*)d_in[2];
    const float* Wout = (const float*)d_in[3];
    const float* bout = (const float*)d_in[4];
    float* out = (float*)d_out;

    // >48KB dynamic smem opt-in for both GEMM instantiations (idempotent)
    cudaFuncSetAttribute(gemm_hmma<0>, cudaFuncAttributeMaxDynamicSharedMemorySize,
                         GEMM_SMEM);
    cudaFuncSetAttribute(gemm_hmma<1>, cudaFuncAttributeMaxDynamicSharedMemorySize,
                         GEMM_SMEM);

    // QKV projection — HMMA double-buffered + ldmatrix, scatter epilogue
    gemm_hmma<0><<<dim3(3 * D_MODEL / 128, M_TOK / 128), 256, GEMM_SMEM>>>(
        x, Wqkv, bqkv, nullptr, 3 * D_MODEL);

    // attention — HMMA flash with ldmatrix fragment loads
    flash_hmma<<<dim3(SEQ_L / 128, BATCH * NUM_HEADS), 256>>>();

    // output projection — HMMA double-buffered + ldmatrix
    gemm_hmma<1><<<dim3(D_MODEL / 128, M_TOK / 128), 256, GEMM_SMEM>>>(
        nullptr, Wout, bout, out, D_MODEL);
}